// round 1
// baseline (speedup 1.0000x reference)
#include <cuda_runtime.h>
#include <cuda_bf16.h>
#include <math.h>

// Problem constants: M=8 modules, B=64 batch, S=128 seq, D=512, H=8 heads (hd=64), FF=1024.

// Scratch (static device array; no runtime allocation).
// Layout (float offsets):
//   q      @ 0         [M][B][D]          262144
//   u      @ 262144    [B][M*H][D]        2097152
//   scores @ 2359296   [B][M*H][S]        524288
//   wv     @ 2883584   [B][M*H][D]        2097152
//   ao     @ 4980736   [M][B][D]          262144
//   x      @ 5242880   [M][B][2D]         524288
//   h      @ 5767168   [4*M][B][FF]       2097152
//   hg     @ 7864320   [4*M][B][FF]       2097152
//   out4   @ 9961472   [4][M][B][D]       1048576
//   gate   @ 11010048  [4*M][B]           2048
__device__ float g_scratch[11012096];

// ---------------------------------------------------------------------------
// Generic batched GEMM: C[64 x N] = act( A[64 x K] @ op(W)[K x N] + bias )
// NT=false: W element (k,n) at W + k*ldw + n   (row-major, N contiguous)
// NT=true : W element (k,n) at W + n*ldw + k   (K contiguous per n-row)
// Per-batch offsets: batch -> (b1 = batch/inner, b0 = batch%inner),
// ptr += b1*s1 + b0*s0 for each operand.
// ACT: 0 = none, 1 = relu, 2 = tanh(relu(.))
// ---------------------------------------------------------------------------
template<int ACT, bool NT>
__global__ __launch_bounds__(256) void gemm64_kernel(
    const float* __restrict__ A, int lda, int sA1, int sA0,
    const float* __restrict__ W, int ldw, int sW1, int sW0,
    float* __restrict__ C, int ldc, int sC1, int sC0,
    const float* __restrict__ bias, int sB1, int sB0,
    int N, int K, int inner)
{
    const int batch = blockIdx.y;
    const int b1 = batch / inner;
    const int b0 = batch - b1 * inner;
    A += (size_t)b1 * sA1 + (size_t)b0 * sA0;
    W += (size_t)b1 * sW1 + (size_t)b0 * sW0;
    C += (size_t)b1 * sC1 + (size_t)b0 * sC0;
    if (bias) bias += b1 * sB1 + b0 * sB0;
    const int n0 = blockIdx.x * 64;

    __shared__ float As[16][68];   // [k][row], padded to dodge bank conflicts
    __shared__ float Ws[16][68];   // [k][col]

    const int tid = threadIdx.x;
    const int tx = tid & 15;       // 16 col-groups of 4
    const int ty = tid >> 4;       // 16 row-groups of 4

    float acc[4][4] = {};

    const int aRow = tid >> 2;            // 0..63
    const int aK   = (tid & 3) << 2;      // 0,4,8,12
    const int wKn  = tid >> 4;            // NN: 0..15
    const int wNn  = (tid & 15) << 2;     // NN: 0..60
    const int wNt  = tid >> 2;            // NT: 0..63
    const int wKt  = (tid & 3) << 2;      // NT: 0,4,8,12

    for (int k0 = 0; k0 < K; k0 += 16) {
        float4 av = *reinterpret_cast<const float4*>(A + (size_t)aRow * lda + (k0 + aK));
        float4 wv4;
        if (NT) {
            wv4 = *reinterpret_cast<const float4*>(W + (size_t)(n0 + wNt) * ldw + (k0 + wKt));
        } else {
            wv4 = *reinterpret_cast<const float4*>(W + (size_t)(k0 + wKn) * ldw + (n0 + wNn));
        }
        __syncthreads();   // previous iteration's reads complete before overwrite
        As[aK + 0][aRow] = av.x;
        As[aK + 1][aRow] = av.y;
        As[aK + 2][aRow] = av.z;
        As[aK + 3][aRow] = av.w;
        if (NT) {
            Ws[wKt + 0][wNt] = wv4.x;
            Ws[wKt + 1][wNt] = wv4.y;
            Ws[wKt + 2][wNt] = wv4.z;
            Ws[wKt + 3][wNt] = wv4.w;
        } else {
            *reinterpret_cast<float4*>(&Ws[wKn][wNn]) = wv4;
        }
        __syncthreads();
        #pragma unroll
        for (int kk = 0; kk < 16; kk++) {
            float4 a4 = *reinterpret_cast<const float4*>(&As[kk][ty << 2]);
            float4 b4 = *reinterpret_cast<const float4*>(&Ws[kk][tx << 2]);
            float aa[4] = {a4.x, a4.y, a4.z, a4.w};
            float bb[4] = {b4.x, b4.y, b4.z, b4.w};
            #pragma unroll
            for (int i = 0; i < 4; i++)
                #pragma unroll
                for (int j = 0; j < 4; j++)
                    acc[i][j] = fmaf(aa[i], bb[j], acc[i][j]);
        }
    }

    #pragma unroll
    for (int i = 0; i < 4; i++) {
        const int row = (ty << 2) + i;
        float ov[4];
        #pragma unroll
        for (int j = 0; j < 4; j++) {
            const int col = n0 + (tx << 2) + j;
            float v = acc[i][j];
            if (bias) v += bias[col];
            if (ACT == 1) v = fmaxf(v, 0.f);
            if (ACT == 2) v = tanhf(fmaxf(v, 0.f));
            ov[j] = v;
        }
        float4 o = make_float4(ov[0], ov[1], ov[2], ov[3]);
        *reinterpret_cast<float4*>(C + (size_t)row * ldc + n0 + (tx << 2)) = o;
    }
}

// Softmax over S=128 per row; rows are contiguous [4096][128]; includes 1/sqrt(hd)=0.125 scale.
__global__ __launch_bounds__(128) void softmax128_kernel(float* __restrict__ p)
{
    __shared__ float red[128];
    float* row = p + (size_t)blockIdx.x * 128;
    const int t = threadIdx.x;
    float v = row[t] * 0.125f;
    red[t] = v;
    __syncthreads();
    for (int s = 64; s > 0; s >>= 1) { if (t < s) red[t] = fmaxf(red[t], red[t + s]); __syncthreads(); }
    const float mx = red[0];
    __syncthreads();
    const float e = __expf(v - mx);
    red[t] = e;
    __syncthreads();
    for (int s = 64; s > 0; s >>= 1) { if (t < s) red[t] += red[t + s]; __syncthreads(); }
    row[t] = e * (1.f / red[0]);
}

// x[m][b][D + d] = relu(prev_state[m][b][d])   (second half of the concat; first half
// is written directly by the attn_out GEMM with ACT=relu)
__global__ __launch_bounds__(256) void build_x2_kernel(const float* __restrict__ ps,
                                                       float* __restrict__ x)
{
    int idx = blockIdx.x * 256 + threadIdx.x;     // M*B*D = 262144 exactly
    int m = idx >> 15;
    int rem = idx & 32767;
    int b = rem >> 9;
    int d = rem & 511;
    x[(size_t)m * 65536 + b * 1024 + 512 + d] = fmaxf(ps[idx], 0.f);
}

// gate[gm*64+b] = sigmoid( dot(hg[gm][b][:], Wg2[gm][:]) + bg2[gm] )
__global__ __launch_bounds__(256) void gate_kernel(const float* __restrict__ hg,
                                                   const float* __restrict__ Wg2,
                                                   const float* __restrict__ bg2,
                                                   float* __restrict__ gate)
{
    const int gm = blockIdx.x >> 6;
    const int b  = blockIdx.x & 63;
    const float* hrow = hg + ((size_t)gm * 64 + b) * 1024;
    const float* w = Wg2 + (size_t)gm * 1024;
    const int t = threadIdx.x;
    float s = 0.f;
    #pragma unroll
    for (int i = t; i < 1024; i += 256) s = fmaf(hrow[i], w[i], s);
    __shared__ float red[256];
    red[t] = s;
    __syncthreads();
    for (int k = 128; k > 0; k >>= 1) { if (t < k) red[t] += red[t + k]; __syncthreads(); }
    if (t == 0) {
        float z = red[0] + bg2[gm];
        gate[blockIdx.x] = 1.f / (1.f + __expf(-z));
    }
}

// out[t][m][b][d] with slot order (state, query, key, value) <- groups (3,0,1,2)
__global__ __launch_bounds__(256) void combine_kernel(
    const float* __restrict__ out4, const float* __restrict__ gate,
    const float* __restrict__ pq, const float* __restrict__ pk,
    const float* __restrict__ pv, const float* __restrict__ ps,
    float* __restrict__ out)
{
    int idx = blockIdx.x * 256 + threadIdx.x;     // 4*M*B*D = 1048576 exactly
    const int t = idx >> 18;          // output slot
    const int r = idx & 262143;       // index within [M,B,D]
    const int g = (t + 3) & 3;        // source group
    const int m = r >> 15;
    const int b = (r >> 9) & 63;
    const float gv = gate[(g * 8 + m) * 64 + b];
    const float o = out4[(size_t)g * 262144 + r];
    const float* prev = (g == 0) ? pq : (g == 1) ? pk : (g == 2) ? pv : ps;
    out[idx] = gv * o + (1.f - gv) * prev[r];
}

extern "C" void kernel_launch(void* const* d_in, const int* in_sizes, int n_in,
                              void* d_out, int out_size)
{
    (void)in_sizes; (void)n_in; (void)out_size;
    const float* prev_state = (const float*)d_in[0];
    const float* prev_query = (const float*)d_in[1];
    const float* prev_key   = (const float*)d_in[2];
    const float* prev_value = (const float*)d_in[3];
    const float* key_in     = (const float*)d_in[4];
    const float* value_in   = (const float*)d_in[5];
    const float* Wq = (const float*)d_in[6];
    const float* bq = (const float*)d_in[7];
    const float* Wk = (const float*)d_in[8];
    // d_in[9] = bk: softmax is invariant to a per-(m,b,h) constant shift over s -> unused.
    const float* Wv = (const float*)d_in[10];
    const float* bv = (const float*)d_in[11];
    const float* Wo = (const float*)d_in[12];
    const float* bo = (const float*)d_in[13];
    const float* W1  = (const float*)d_in[14];
    const float* b1  = (const float*)d_in[15];
    const float* W2  = (const float*)d_in[16];
    const float* b2  = (const float*)d_in[17];
    const float* Wg1 = (const float*)d_in[18];
    const float* bg1 = (const float*)d_in[19];
    const float* Wg2 = (const float*)d_in[20];
    const float* bg2 = (const float*)d_in[21];
    float* out = (float*)d_out;

    float* scratch = nullptr;
    cudaGetSymbolAddress((void**)&scratch, g_scratch);
    float* q    = scratch;
    float* u    = scratch + 262144;
    float* sc   = scratch + 2359296;
    float* wvb  = scratch + 2883584;
    float* ao   = scratch + 4980736;
    float* x    = scratch + 5242880;
    float* h    = scratch + 5767168;
    float* hg   = scratch + 7864320;
    float* out4 = scratch + 9961472;
    float* gate = scratch + 11010048;

    // 1) q = prev_query @ Wq + bq              per m:   [64x512]@[512x512]
    gemm64_kernel<0,false><<<dim3(8,8),256>>>(
        prev_query,512,32768,0,  Wq,512,262144,0,  q,512,32768,0,  bq,512,0,  512,512,1);

    // 2) u[b][mh][d] = sum_j Wk[m][d][h*64+j] * q[m][b][h*64+j]   per (m,h): NT [64x512], K=64
    gemm64_kernel<0,true><<<dim3(8,64),256>>>(
        q,512,32768,64,  Wk,512,262144,64,  u,32768,4096,512,  (const float*)nullptr,0,0,  512,64,8);

    // 3) scores[b][mh][s] = sum_d u[b][mh][d] * key_in[s][b][d]   per b: NT [64x128], K=512
    gemm64_kernel<0,true><<<dim3(2,64),256>>>(
        u,512,32768,0,  key_in,32768,512,0,  sc,128,8192,0,  (const float*)nullptr,0,0,  128,512,1);

    // 4) softmax over s (with 1/sqrt(hd) scale)
    softmax128_kernel<<<4096,128>>>(sc);

    // 5) wv[b][mh][d] = sum_s w[b][mh][s] * value_in[s][b][d]     per b: NN [64x512], K=128
    gemm64_kernel<0,false><<<dim3(8,64),256>>>(
        sc,128,8192,0,  value_in,32768,512,0,  wvb,512,32768,0,  (const float*)nullptr,0,0,  512,128,1);

    // 6) ao[m][b][h*64+j] = sum_d wv[b][mh][d]*Wv[m][d][h*64+j] + bv   per (m,h): NN [64x64], K=512
    gemm64_kernel<0,false><<<dim3(1,64),256>>>(
        wvb,32768,4096,512,  Wv,512,262144,64,  ao,512,32768,64,  bv,512,64,  64,512,8);

    // 7) x[:, :D] = relu(ao @ Wo + bo)          per m: NN [64x512], K=512, writes into x (ldc=1024)
    gemm64_kernel<1,false><<<dim3(8,8),256>>>(
        ao,512,32768,0,  Wo,512,262144,0,  x,1024,65536,0,  bo,512,0,  512,512,1);

    // 8) x[:, D:] = relu(prev_state)
    build_x2_kernel<<<1024,256>>>(prev_state, x);

    // 9) h = relu(x @ W1 + b1)                  per (g,m): NN [64x1024], K=1024
    gemm64_kernel<1,false><<<dim3(16,32),256>>>(
        x,1024,0,65536,  W1,1024,8388608,1048576,  h,1024,524288,65536,  b1,8192,1024,  1024,1024,8);

    // 10) hg = relu(x @ Wg1 + bg1)
    gemm64_kernel<1,false><<<dim3(16,32),256>>>(
        x,1024,0,65536,  Wg1,1024,8388608,1048576,  hg,1024,524288,65536,  bg1,8192,1024,  1024,1024,8);

    // 11) out4 = tanh(relu(h @ W2 + b2))        per (g,m): NN [64x512], K=1024
    gemm64_kernel<2,false><<<dim3(8,32),256>>>(
        h,1024,524288,65536,  W2,512,4194304,524288,  out4,512,262144,32768,  b2,4096,512,  512,1024,8);

    // 12) gate = sigmoid(hg @ Wg2 + bg2)
    gate_kernel<<<2048,256>>>(hg, Wg2, bg2, gate);

    // 13) combine + reorder to (state, query, key, value)
    combine_kernel<<<4096,256>>>(out4, gate, prev_query, prev_key, prev_value, prev_state, out);
}

// round 5
// speedup vs baseline: 2.0156x; 2.0156x over previous
#include <cuda_runtime.h>
#include <cuda_bf16.h>
#include <math.h>
#include <stdint.h>

// Problem constants: M=8 modules, B=64 batch, S=128 seq, D=512, H=8 heads (hd=64), FF=1024.

// Scratch (static device array; no runtime allocation).
__device__ float g_scratch[11012096];

__device__ __forceinline__ uint32_t cvt_tf32(float x){
    uint32_t r; asm("cvt.rna.tf32.f32 %0, %1;" : "=r"(r) : "f"(x)); return r;
}

// ===========================================================================
// tf32 mma.sync GEMM: C[64 x Ntot] = act( A[64 x K] @ W[K x Ntot] + bias )
// A: K-major fp32, per-batch A = A + (b & aMask)*sA.
// W: element (k,n) at W + b*sW + k*ldw + n   (N contiguous within a row).
// C: C + b*sC + row*ldc + n.  bias: bias + b*sBias + n (nullptr ok).
// Block: 256 threads (8 warps = 2 m-warps x 4 n-warps), CTA tile 64x128,
// K-chunk 32, warp tile 32x32 via m16n8k8 tf32 mma.sync atoms.
// ACT: 0 none, 1 relu, 2 tanh(relu)
// ===========================================================================
template<int ACT>
__global__ __launch_bounds__(256) void mma_gemm_kernel(
    const float* __restrict__ A, int lda, int sA, int aMask,
    const float* __restrict__ W, int ldw, size_t sW,
    float* __restrict__ C, int ldc, int sC,
    const float* __restrict__ bias, int sBias, int K)
{
    __shared__ float As[64][36];    // [row][k], padded
    __shared__ float Bs[32][132];   // [k][n],  padded

    const int tid = threadIdx.x;
    const int wid = tid >> 5, lane = tid & 31;
    const int g = lane >> 2, tig = lane & 3;
    const int warp_m = wid >> 2;         // 0..1 -> rows 32*warp_m
    const int warp_n = wid & 3;          // 0..3 -> cols 32*warp_n
    const int b = blockIdx.y;
    const int n0 = blockIdx.x * 128;

    const float* Ab = A + (size_t)(b & aMask) * sA;
    const float* Wb = W + (size_t)b * sW + n0;
    float*       Cb = C + (size_t)b * sC + n0;
    const float* Bb = bias ? bias + (size_t)b * sBias + n0 : nullptr;

    uint32_t* Asu = reinterpret_cast<uint32_t*>(&As[0][0]);
    uint32_t* Bsu = reinterpret_cast<uint32_t*>(&Bs[0][0]);

    const int NC = K >> 5;

    float4 aR[2], bR[4];
    auto ldg = [&](int c){
        const int k0 = c << 5;
        #pragma unroll
        for (int i = 0; i < 2; i++){
            int f = tid + (i << 8);          // 0..511
            int r = f >> 3, kq = f & 7;      // 64 rows x 8 float4
            aR[i] = *reinterpret_cast<const float4*>(Ab + (size_t)r * lda + k0 + (kq << 2));
        }
        #pragma unroll
        for (int i = 0; i < 4; i++){
            int f = tid + (i << 8);          // 0..1023
            int k = f >> 5, nq = f & 31;     // 32 k-rows x 32 float4
            bR[i] = *reinterpret_cast<const float4*>(Wb + (size_t)(k0 + k) * ldw + (nq << 2));
        }
    };
    auto sts = [&](){
        #pragma unroll
        for (int i = 0; i < 2; i++){
            int f = tid + (i << 8);
            int r = f >> 3, kq = f & 7;
            uint4 v = make_uint4(cvt_tf32(aR[i].x), cvt_tf32(aR[i].y),
                                 cvt_tf32(aR[i].z), cvt_tf32(aR[i].w));
            *reinterpret_cast<uint4*>(&Asu[r * 36 + (kq << 2)]) = v;
        }
        #pragma unroll
        for (int i = 0; i < 4; i++){
            int f = tid + (i << 8);
            int k = f >> 5, nq = f & 31;
            uint4 v = make_uint4(cvt_tf32(bR[i].x), cvt_tf32(bR[i].y),
                                 cvt_tf32(bR[i].z), cvt_tf32(bR[i].w));
            *reinterpret_cast<uint4*>(&Bsu[k * 132 + (nq << 2)]) = v;
        }
    };

    float acc[2][4][4];
    #pragma unroll
    for (int i = 0; i < 2; i++)
        #pragma unroll
        for (int j = 0; j < 4; j++)
            #pragma unroll
            for (int u = 0; u < 4; u++) acc[i][j][u] = 0.f;

    ldg(0);
    for (int c = 0; c < NC; ++c){
        __syncthreads();
        sts();
        __syncthreads();
        if (c + 1 < NC) ldg(c + 1);
        #pragma unroll
        for (int ks = 0; ks < 4; ks++){
            const int kk = ks << 3;
            uint32_t af[2][4];
            #pragma unroll
            for (int ma = 0; ma < 2; ma++){
                const int r0 = warp_m * 32 + ma * 16 + g;
                af[ma][0] = Asu[r0 * 36 + kk + tig];
                af[ma][1] = Asu[(r0 + 8) * 36 + kk + tig];
                af[ma][2] = Asu[r0 * 36 + kk + tig + 4];
                af[ma][3] = Asu[(r0 + 8) * 36 + kk + tig + 4];
            }
            uint32_t bf[4][2];
            #pragma unroll
            for (int na = 0; na < 4; na++){
                const int cl = warp_n * 32 + na * 8 + g;
                bf[na][0] = Bsu[(kk + tig) * 132 + cl];
                bf[na][1] = Bsu[(kk + tig + 4) * 132 + cl];
            }
            #pragma unroll
            for (int ma = 0; ma < 2; ma++)
                #pragma unroll
                for (int na = 0; na < 4; na++){
                    asm volatile(
                        "mma.sync.aligned.m16n8k8.row.col.f32.tf32.tf32.f32 "
                        "{%0,%1,%2,%3}, {%4,%5,%6,%7}, {%8,%9}, {%0,%1,%2,%3};"
                        : "+f"(acc[ma][na][0]), "+f"(acc[ma][na][1]),
                          "+f"(acc[ma][na][2]), "+f"(acc[ma][na][3])
                        : "r"(af[ma][0]), "r"(af[ma][1]), "r"(af[ma][2]), "r"(af[ma][3]),
                          "r"(bf[na][0]), "r"(bf[na][1]));
                }
        }
    }

    // Epilogue
    #pragma unroll
    for (int ma = 0; ma < 2; ma++){
        const int r0 = warp_m * 32 + ma * 16 + g;
        #pragma unroll
        for (int na = 0; na < 4; na++){
            const int cl = warp_n * 32 + na * 8 + 2 * tig;
            float b0 = Bb ? Bb[cl] : 0.f;
            float b1 = Bb ? Bb[cl + 1] : 0.f;
            float v0 = acc[ma][na][0] + b0, v1 = acc[ma][na][1] + b1;
            float v2 = acc[ma][na][2] + b0, v3 = acc[ma][na][3] + b1;
            if (ACT >= 1){
                v0 = fmaxf(v0, 0.f); v1 = fmaxf(v1, 0.f);
                v2 = fmaxf(v2, 0.f); v3 = fmaxf(v3, 0.f);
            }
            if (ACT == 2){
                v0 = tanhf(v0); v1 = tanhf(v1); v2 = tanhf(v2); v3 = tanhf(v3);
            }
            *reinterpret_cast<float2*>(Cb + (size_t)r0 * ldc + cl) = make_float2(v0, v1);
            *reinterpret_cast<float2*>(Cb + (size_t)(r0 + 8) * ldc + cl) = make_float2(v2, v3);
        }
    }
}

// ===========================================================================
// FFMA GEMM for the odd-shaped attention matmuls (NT / N=64)
// ===========================================================================
template<int ACT, bool NT>
__global__ __launch_bounds__(256) void gemm64_kernel(
    const float* __restrict__ A, int lda, int sA1, int sA0,
    const float* __restrict__ W, int ldw, int sW1, int sW0,
    float* __restrict__ C, int ldc, int sC1, int sC0,
    const float* __restrict__ bias, int sB1, int sB0,
    int N, int K, int inner)
{
    const int batch = blockIdx.y;
    const int b1 = batch / inner;
    const int b0 = batch - b1 * inner;
    A += (size_t)b1 * sA1 + (size_t)b0 * sA0;
    W += (size_t)b1 * sW1 + (size_t)b0 * sW0;
    C += (size_t)b1 * sC1 + (size_t)b0 * sC0;
    if (bias) bias += b1 * sB1 + b0 * sB0;
    const int n0 = blockIdx.x * 64;

    __shared__ float As[16][68];
    __shared__ float Ws[16][68];

    const int tid = threadIdx.x;
    const int tx = tid & 15;
    const int ty = tid >> 4;

    float acc[4][4] = {};

    const int aRow = tid >> 2;
    const int aK   = (tid & 3) << 2;
    const int wKn  = tid >> 4;
    const int wNn  = (tid & 15) << 2;
    const int wNt  = tid >> 2;
    const int wKt  = (tid & 3) << 2;

    for (int k0 = 0; k0 < K; k0 += 16) {
        float4 av = *reinterpret_cast<const float4*>(A + (size_t)aRow * lda + (k0 + aK));
        float4 wv4;
        if (NT) {
            wv4 = *reinterpret_cast<const float4*>(W + (size_t)(n0 + wNt) * ldw + (k0 + wKt));
        } else {
            wv4 = *reinterpret_cast<const float4*>(W + (size_t)(k0 + wKn) * ldw + (n0 + wNn));
        }
        __syncthreads();
        As[aK + 0][aRow] = av.x;
        As[aK + 1][aRow] = av.y;
        As[aK + 2][aRow] = av.z;
        As[aK + 3][aRow] = av.w;
        if (NT) {
            Ws[wKt + 0][wNt] = wv4.x;
            Ws[wKt + 1][wNt] = wv4.y;
            Ws[wKt + 2][wNt] = wv4.z;
            Ws[wKt + 3][wNt] = wv4.w;
        } else {
            *reinterpret_cast<float4*>(&Ws[wKn][wNn]) = wv4;
        }
        __syncthreads();
        #pragma unroll
        for (int kk = 0; kk < 16; kk++) {
            float4 a4 = *reinterpret_cast<const float4*>(&As[kk][ty << 2]);
            float4 b4 = *reinterpret_cast<const float4*>(&Ws[kk][tx << 2]);
            float aa[4] = {a4.x, a4.y, a4.z, a4.w};
            float bb[4] = {b4.x, b4.y, b4.z, b4.w};
            #pragma unroll
            for (int i = 0; i < 4; i++)
                #pragma unroll
                for (int j = 0; j < 4; j++)
                    acc[i][j] = fmaf(aa[i], bb[j], acc[i][j]);
        }
    }

    #pragma unroll
    for (int i = 0; i < 4; i++) {
        const int row = (ty << 2) + i;
        float ov[4];
        #pragma unroll
        for (int j = 0; j < 4; j++) {
            const int col = n0 + (tx << 2) + j;
            float v = acc[i][j];
            if (bias) v += bias[col];
            if (ACT == 1) v = fmaxf(v, 0.f);
            if (ACT == 2) v = tanhf(fmaxf(v, 0.f));
            ov[j] = v;
        }
        float4 o = make_float4(ov[0], ov[1], ov[2], ov[3]);
        *reinterpret_cast<float4*>(C + (size_t)row * ldc + n0 + (tx << 2)) = o;
    }
}

__global__ __launch_bounds__(128) void softmax128_kernel(float* __restrict__ p)
{
    __shared__ float red[128];
    float* row = p + (size_t)blockIdx.x * 128;
    const int t = threadIdx.x;
    float v = row[t] * 0.125f;
    red[t] = v;
    __syncthreads();
    for (int s = 64; s > 0; s >>= 1) { if (t < s) red[t] = fmaxf(red[t], red[t + s]); __syncthreads(); }
    const float mx = red[0];
    __syncthreads();
    const float e = __expf(v - mx);
    red[t] = e;
    __syncthreads();
    for (int s = 64; s > 0; s >>= 1) { if (t < s) red[t] += red[t + s]; __syncthreads(); }
    row[t] = e * (1.f / red[0]);
}

__global__ __launch_bounds__(256) void build_x2_kernel(const float* __restrict__ ps,
                                                       float* __restrict__ x)
{
    int idx = blockIdx.x * 256 + threadIdx.x;
    int m = idx >> 15;
    int rem = idx & 32767;
    int b = rem >> 9;
    int d = rem & 511;
    x[(size_t)m * 65536 + b * 1024 + 512 + d] = fmaxf(ps[idx], 0.f);
}

__global__ __launch_bounds__(256) void gate_kernel(const float* __restrict__ hg,
                                                   const float* __restrict__ Wg2,
                                                   const float* __restrict__ bg2,
                                                   float* __restrict__ gate)
{
    const int gm = blockIdx.x >> 6;
    const int b  = blockIdx.x & 63;
    const float* hrow = hg + ((size_t)gm * 64 + b) * 1024;
    const float* w = Wg2 + (size_t)gm * 1024;
    const int t = threadIdx.x;
    float s = 0.f;
    #pragma unroll
    for (int i = t; i < 1024; i += 256) s = fmaf(hrow[i], w[i], s);
    __shared__ float red[256];
    red[t] = s;
    __syncthreads();
    for (int k = 128; k > 0; k >>= 1) { if (t < k) red[t] += red[t + k]; __syncthreads(); }
    if (t == 0) {
        float z = red[0] + bg2[gm];
        gate[blockIdx.x] = 1.f / (1.f + __expf(-z));
    }
}

__global__ __launch_bounds__(256) void combine_kernel(
    const float* __restrict__ out4, const float* __restrict__ gate,
    const float* __restrict__ pq, const float* __restrict__ pk,
    const float* __restrict__ pv, const float* __restrict__ ps,
    float* __restrict__ out)
{
    int idx = blockIdx.x * 256 + threadIdx.x;
    const int t = idx >> 18;
    const int r = idx & 262143;
    const int g = (t + 3) & 3;
    const int m = r >> 15;
    const int b = (r >> 9) & 63;
    const float gv = gate[(g * 8 + m) * 64 + b];
    const float o = out4[(size_t)g * 262144 + r];
    const float* prev = (g == 0) ? pq : (g == 1) ? pk : (g == 2) ? pv : ps;
    out[idx] = gv * o + (1.f - gv) * prev[r];
}

extern "C" void kernel_launch(void* const* d_in, const int* in_sizes, int n_in,
                              void* d_out, int out_size)
{
    (void)in_sizes; (void)n_in; (void)out_size;
    const float* prev_state = (const float*)d_in[0];
    const float* prev_query = (const float*)d_in[1];
    const float* prev_key   = (const float*)d_in[2];
    const float* prev_value = (const float*)d_in[3];
    const float* key_in     = (const float*)d_in[4];
    const float* value_in   = (const float*)d_in[5];
    const float* Wq = (const float*)d_in[6];
    const float* bq = (const float*)d_in[7];
    const float* Wk = (const float*)d_in[8];
    // d_in[9] = bk: softmax invariant to per-(m,b,h) shift over s -> unused.
    const float* Wv = (const float*)d_in[10];
    const float* bv = (const float*)d_in[11];
    const float* Wo = (const float*)d_in[12];
    const float* bo = (const float*)d_in[13];
    const float* W1  = (const float*)d_in[14];
    const float* b1  = (const float*)d_in[15];
    const float* W2  = (const float*)d_in[16];
    const float* b2  = (const float*)d_in[17];
    const float* Wg1 = (const float*)d_in[18];
    const float* bg1 = (const float*)d_in[19];
    const float* Wg2 = (const float*)d_in[20];
    const float* bg2 = (const float*)d_in[21];
    float* out = (float*)d_out;

    float* scratch = nullptr;
    cudaGetSymbolAddress((void**)&scratch, g_scratch);
    float* q    = scratch;
    float* u    = scratch + 262144;
    float* sc   = scratch + 2359296;
    float* wvb  = scratch + 2883584;
    float* ao   = scratch + 4980736;
    float* x    = scratch + 5242880;
    float* h    = scratch + 5767168;
    float* hg   = scratch + 7864320;
    float* out4 = scratch + 9961472;
    float* gate = scratch + 11010048;

    // 1) q = prev_query @ Wq + bq          (tf32 mma)  per m: [64x512]@[512x512]
    mma_gemm_kernel<0><<<dim3(4,8),256>>>(
        prev_query,512,32768,7,  Wq,512,(size_t)262144,  q,512,32768,  bq,512, 512);

    // 2) u[b][mh][d] = sum_j Wk[m][d][h*64+j] * q[m][b][h*64+j]   (FFMA NT, K=64)
    gemm64_kernel<0,true><<<dim3(8,64),256>>>(
        q,512,32768,64,  Wk,512,262144,64,  u,32768,4096,512,  (const float*)nullptr,0,0,  512,64,8);

    // 3) scores[b][mh][s] = sum_d u[b][mh][d] * key_in[s][b][d]   (FFMA NT, K=512)
    gemm64_kernel<0,true><<<dim3(2,64),256>>>(
        u,512,32768,0,  key_in,32768,512,0,  sc,128,8192,0,  (const float*)nullptr,0,0,  128,512,1);

    // 4) softmax over s
    softmax128_kernel<<<4096,128>>>(sc);

    // 5) wv[b][mh][d] = sum_s w[b][mh][s] * value_in[s][b][d]   (tf32 mma, K=128)
    //    W element (k=s, n=d) at value_in + s*32768 + b*512 + d
    mma_gemm_kernel<0><<<dim3(4,64),256>>>(
        sc,128,8192,63,  value_in,32768,(size_t)512,  wvb,512,32768,  (const float*)nullptr,0, 128);

    // 6) ao = wv @ Wv-slices + bv          (FFMA, N=64)
    gemm64_kernel<0,false><<<dim3(1,64),256>>>(
        wvb,32768,4096,512,  Wv,512,262144,64,  ao,512,32768,64,  bv,512,64,  64,512,8);

    // 7) x[:, :D] = relu(ao @ Wo + bo)     (tf32 mma)
    mma_gemm_kernel<1><<<dim3(4,8),256>>>(
        ao,512,32768,7,  Wo,512,(size_t)262144,  x,1024,65536,  bo,512, 512);

    // 8) x[:, D:] = relu(prev_state)
    build_x2_kernel<<<1024,256>>>(prev_state, x);

    // 9) h = relu(x @ W1 + b1)             (tf32 mma) batches (g,m), A = x[m]
    mma_gemm_kernel<1><<<dim3(8,32),256>>>(
        x,1024,65536,7,  W1,1024,(size_t)1048576,  h,1024,65536,  b1,1024, 1024);

    // 10) hg = relu(x @ Wg1 + bg1)         (tf32 mma)
    mma_gemm_kernel<1><<<dim3(8,32),256>>>(
        x,1024,65536,7,  Wg1,1024,(size_t)1048576,  hg,1024,65536,  bg1,1024, 1024);

    // 11) out4 = tanh(relu(h @ W2 + b2))   (tf32 mma)
    mma_gemm_kernel<2><<<dim3(4,32),256>>>(
        h,1024,65536,63,  W2,512,(size_t)524288,  out4,512,32768,  b2,512, 1024);

    // 12) gate = sigmoid(hg @ Wg2 + bg2)
    gate_kernel<<<2048,256>>>(hg, Wg2, bg2, gate);

    // 13) combine + reorder to (state, query, key, value)
    combine_kernel<<<4096,256>>>(out4, gate, prev_query, prev_key, prev_value, prev_state, out);
}

// round 6
// speedup vs baseline: 2.4830x; 1.2319x over previous
#include <cuda_runtime.h>
#include <cuda_bf16.h>
#include <math.h>
#include <stdint.h>

// Problem constants: M=8 modules, B=64 batch, S=128 seq, D=512, H=8 heads (hd=64), FF=1024.

// Scratch (static device array; no runtime allocation).
__device__ float g_scratch[11012096];

__device__ __forceinline__ uint32_t cvt_tf32(float x){
    uint32_t r; asm("cvt.rna.tf32.f32 %0, %1;" : "=r"(r) : "f"(x)); return r;
}

// ===========================================================================
// tf32 mma.sync GEMM, generalized + double-buffered.
//   C[64 x N] = act( A[64 x K] @ W[K x N] + bias )   per batch
// Batch decomposition: b1 = batch / inner, b0 = batch % inner; each operand
// offset = b1*s1 + b0*s0.
// A: element (row,k) at A + row*lda + k          (k contiguous)
// W: BNT=false: (k,n) at W + k*ldw + n           (n contiguous)
//    BNT=true : (k,n) at W + n*ldw + k           (k contiguous)
// BN: CTA N-tile (64 or 128). grid.x = N/BN. Block: 256 threads, 8 warps
// (2 m-warps x 4 n-warps), warp tile 32 x BN/4, m16n8k8 tf32 atoms.
// 2-stage SMEM pipeline: one __syncthreads per K-chunk of 32.
// ACT: 0 none, 1 relu, 2 tanh(relu)
// ===========================================================================
template<int ACT, bool BNT, int BN>
__global__ __launch_bounds__(256) void mma_gemm_kernel(
    const float* __restrict__ A, int lda, int sA1, int sA0,
    const float* __restrict__ W, int ldw, int sW1, int sW0,
    float* __restrict__ C, int ldc, int sC1, int sC0,
    const float* __restrict__ bias, int sB1, int sB0,
    int K, int inner)
{
    extern __shared__ float smemf[];
    constexpr int A_F = 64 * 36;                 // A stage floats
    constexpr int BSTR = BN + 4;                 // B row stride
    constexpr int STAGE_F = A_F + 32 * BSTR;     // stage floats

    const int tid = threadIdx.x;
    const int wid = tid >> 5, lane = tid & 31;
    const int g = lane >> 2, tig = lane & 3;
    const int warp_m = wid >> 2;                 // 0..1
    const int warp_n = wid & 3;                  // 0..3
    const int batch = blockIdx.y;
    const int b1 = batch / inner;
    const int b0 = batch - b1 * inner;
    const int n0 = blockIdx.x * BN;

    const float* Ab = A + (size_t)b1 * sA1 + (size_t)b0 * sA0;
    const float* Wb = W + (size_t)b1 * sW1 + (size_t)b0 * sW0
                        + (BNT ? (size_t)n0 * ldw : (size_t)n0);
    float*       Cb = C + (size_t)b1 * sC1 + (size_t)b0 * sC0 + n0;
    const float* Bb = bias ? bias + (size_t)b1 * sB1 + (size_t)b0 * sB0 + n0 : nullptr;

    const int NC = K >> 5;
    constexpr int BITER = BN / 32;               // B ldg iterations

    float4 aR[2], bR[BITER];
    auto ldg = [&](int c){
        const int k0 = c << 5;
        #pragma unroll
        for (int i = 0; i < 2; i++){
            int f = tid + (i << 8);              // 0..511
            int r = f >> 3, kq = f & 7;          // 64 rows x 8 float4
            aR[i] = *reinterpret_cast<const float4*>(Ab + (size_t)r * lda + k0 + (kq << 2));
        }
        #pragma unroll
        for (int i = 0; i < BITER; i++){
            int f = tid + (i << 8);
            if (BNT){
                int n = f >> 3, kq = f & 7;      // BN n-rows x 8 k-quads
                bR[i] = *reinterpret_cast<const float4*>(Wb + (size_t)n * ldw + k0 + (kq << 2));
            } else {
                int k = f / (BN >> 2), nq = f % (BN >> 2);
                bR[i] = *reinterpret_cast<const float4*>(Wb + (size_t)(k0 + k) * ldw + (nq << 2));
            }
        }
    };
    auto sts = [&](int s){
        uint32_t* Au = reinterpret_cast<uint32_t*>(smemf + s * STAGE_F);
        uint32_t* Bu = reinterpret_cast<uint32_t*>(smemf + s * STAGE_F + A_F);
        #pragma unroll
        for (int i = 0; i < 2; i++){
            int f = tid + (i << 8);
            int r = f >> 3, kq = f & 7;
            uint4 v = make_uint4(cvt_tf32(aR[i].x), cvt_tf32(aR[i].y),
                                 cvt_tf32(aR[i].z), cvt_tf32(aR[i].w));
            *reinterpret_cast<uint4*>(&Au[r * 36 + (kq << 2)]) = v;
        }
        #pragma unroll
        for (int i = 0; i < BITER; i++){
            int f = tid + (i << 8);
            if (BNT){
                int n = f >> 3, kq = f & 7;
                Bu[(4 * kq + 0) * BSTR + n] = cvt_tf32(bR[i].x);
                Bu[(4 * kq + 1) * BSTR + n] = cvt_tf32(bR[i].y);
                Bu[(4 * kq + 2) * BSTR + n] = cvt_tf32(bR[i].z);
                Bu[(4 * kq + 3) * BSTR + n] = cvt_tf32(bR[i].w);
            } else {
                int k = f / (BN >> 2), nq = f % (BN >> 2);
                uint4 v = make_uint4(cvt_tf32(bR[i].x), cvt_tf32(bR[i].y),
                                     cvt_tf32(bR[i].z), cvt_tf32(bR[i].w));
                *reinterpret_cast<uint4*>(&Bu[k * BSTR + (nq << 2)]) = v;
            }
        }
    };

    constexpr int NA = BN / 32;                  // n-atoms per warp (pairs of n8)
    float acc[2][NA][4];
    #pragma unroll
    for (int i = 0; i < 2; i++)
        #pragma unroll
        for (int j = 0; j < NA; j++)
            #pragma unroll
            for (int u = 0; u < 4; u++) acc[i][j][u] = 0.f;

    ldg(0);
    sts(0);
    if (NC > 1) ldg(1);
    __syncthreads();

    for (int c = 0; c < NC; ++c){
        const int s = c & 1;
        if (c + 1 < NC){
            sts(s ^ 1);
            if (c + 2 < NC) ldg(c + 2);
        }
        const uint32_t* Au = reinterpret_cast<const uint32_t*>(smemf + s * STAGE_F);
        const uint32_t* Bu = reinterpret_cast<const uint32_t*>(smemf + s * STAGE_F + A_F);
        #pragma unroll
        for (int ks = 0; ks < 4; ks++){
            const int kk = ks << 3;
            uint32_t af[2][4];
            #pragma unroll
            for (int ma = 0; ma < 2; ma++){
                const int r0 = warp_m * 32 + ma * 16 + g;
                af[ma][0] = Au[r0 * 36 + kk + tig];
                af[ma][1] = Au[(r0 + 8) * 36 + kk + tig];
                af[ma][2] = Au[r0 * 36 + kk + tig + 4];
                af[ma][3] = Au[(r0 + 8) * 36 + kk + tig + 4];
            }
            uint32_t bf[NA][2];
            #pragma unroll
            for (int na = 0; na < NA; na++){
                const int cl = warp_n * (BN / 4) + na * 8 + g;
                bf[na][0] = Bu[(kk + tig) * BSTR + cl];
                bf[na][1] = Bu[(kk + tig + 4) * BSTR + cl];
            }
            #pragma unroll
            for (int ma = 0; ma < 2; ma++)
                #pragma unroll
                for (int na = 0; na < NA; na++){
                    asm volatile(
                        "mma.sync.aligned.m16n8k8.row.col.f32.tf32.tf32.f32 "
                        "{%0,%1,%2,%3}, {%4,%5,%6,%7}, {%8,%9}, {%0,%1,%2,%3};"
                        : "+f"(acc[ma][na][0]), "+f"(acc[ma][na][1]),
                          "+f"(acc[ma][na][2]), "+f"(acc[ma][na][3])
                        : "r"(af[ma][0]), "r"(af[ma][1]), "r"(af[ma][2]), "r"(af[ma][3]),
                          "r"(bf[na][0]), "r"(bf[na][1]));
                }
        }
        __syncthreads();
    }

    // Epilogue
    #pragma unroll
    for (int ma = 0; ma < 2; ma++){
        const int r0 = warp_m * 32 + ma * 16 + g;
        #pragma unroll
        for (int na = 0; na < NA; na++){
            const int cl = warp_n * (BN / 4) + na * 8 + 2 * tig;
            float b0 = Bb ? Bb[cl] : 0.f;
            float b1 = Bb ? Bb[cl + 1] : 0.f;
            float v0 = acc[ma][na][0] + b0, v1 = acc[ma][na][1] + b1;
            float v2 = acc[ma][na][2] + b0, v3 = acc[ma][na][3] + b1;
            if (ACT >= 1){
                v0 = fmaxf(v0, 0.f); v1 = fmaxf(v1, 0.f);
                v2 = fmaxf(v2, 0.f); v3 = fmaxf(v3, 0.f);
            }
            if (ACT == 2){
                v0 = tanhf(v0); v1 = tanhf(v1); v2 = tanhf(v2); v3 = tanhf(v3);
            }
            *reinterpret_cast<float2*>(Cb + (size_t)r0 * ldc + cl) = make_float2(v0, v1);
            *reinterpret_cast<float2*>(Cb + (size_t)(r0 + 8) * ldc + cl) = make_float2(v2, v3);
        }
    }
}

// Warp-per-row softmax over S=128 (4096 rows); includes 1/sqrt(hd)=0.125 scale.
__global__ __launch_bounds__(256) void softmax128_warp_kernel(float* __restrict__ p)
{
    const int row = blockIdx.x * 8 + (threadIdx.x >> 5);
    const int lane = threadIdx.x & 31;
    float4* r4 = reinterpret_cast<float4*>(p + (size_t)row * 128) + lane;
    float4 v = *r4;
    v.x *= 0.125f; v.y *= 0.125f; v.z *= 0.125f; v.w *= 0.125f;
    float mx = fmaxf(fmaxf(v.x, v.y), fmaxf(v.z, v.w));
    #pragma unroll
    for (int o = 16; o > 0; o >>= 1) mx = fmaxf(mx, __shfl_xor_sync(0xffffffffu, mx, o));
    float e0 = __expf(v.x - mx), e1 = __expf(v.y - mx);
    float e2 = __expf(v.z - mx), e3 = __expf(v.w - mx);
    float sm = e0 + e1 + e2 + e3;
    #pragma unroll
    for (int o = 16; o > 0; o >>= 1) sm += __shfl_xor_sync(0xffffffffu, sm, o);
    const float inv = 1.f / sm;
    *r4 = make_float4(e0 * inv, e1 * inv, e2 * inv, e3 * inv);
}

// x[m][b][D + d] = relu(prev_state[m][b][d])
__global__ __launch_bounds__(256) void build_x2_kernel(const float* __restrict__ ps,
                                                       float* __restrict__ x)
{
    int idx = blockIdx.x * 256 + threadIdx.x;
    int m = idx >> 15;
    int rem = idx & 32767;
    int b = rem >> 9;
    int d = rem & 511;
    x[(size_t)m * 65536 + b * 1024 + 512 + d] = fmaxf(ps[idx], 0.f);
}

// gate[gm*64+b] = sigmoid( dot(hg[gm][b][:], Wg2[gm][:]) + bg2[gm] )
__global__ __launch_bounds__(256) void gate_kernel(const float* __restrict__ hg,
                                                   const float* __restrict__ Wg2,
                                                   const float* __restrict__ bg2,
                                                   float* __restrict__ gate)
{
    const int gm = blockIdx.x >> 6;
    const int b  = blockIdx.x & 63;
    const float* hrow = hg + ((size_t)gm * 64 + b) * 1024;
    const float* w = Wg2 + (size_t)gm * 1024;
    const int t = threadIdx.x;
    float s = 0.f;
    #pragma unroll
    for (int i = t; i < 1024; i += 256) s = fmaf(hrow[i], w[i], s);
    __shared__ float red[256];
    red[t] = s;
    __syncthreads();
    for (int k = 128; k > 0; k >>= 1) { if (t < k) red[t] += red[t + k]; __syncthreads(); }
    if (t == 0) {
        float z = red[0] + bg2[gm];
        gate[blockIdx.x] = 1.f / (1.f + __expf(-z));
    }
}

// out[t][m][b][d], slot order (state, query, key, value) <- groups (3,0,1,2)
__global__ __launch_bounds__(256) void combine_kernel(
    const float* __restrict__ out4, const float* __restrict__ gate,
    const float* __restrict__ pq, const float* __restrict__ pk,
    const float* __restrict__ pv, const float* __restrict__ ps,
    float* __restrict__ out)
{
    int idx = blockIdx.x * 256 + threadIdx.x;
    const int t = idx >> 18;
    const int r = idx & 262143;
    const int g = (t + 3) & 3;
    const int m = r >> 15;
    const int b = (r >> 9) & 63;
    const float gv = gate[(g * 8 + m) * 64 + b];
    const float o = out4[(size_t)g * 262144 + r];
    const float* prev = (g == 0) ? pq : (g == 1) ? pk : (g == 2) ? pv : ps;
    out[idx] = gv * o + (1.f - gv) * prev[r];
}

extern "C" void kernel_launch(void* const* d_in, const int* in_sizes, int n_in,
                              void* d_out, int out_size)
{
    (void)in_sizes; (void)n_in; (void)out_size;
    const float* prev_state = (const float*)d_in[0];
    const float* prev_query = (const float*)d_in[1];
    const float* prev_key   = (const float*)d_in[2];
    const float* prev_value = (const float*)d_in[3];
    const float* key_in     = (const float*)d_in[4];
    const float* value_in   = (const float*)d_in[5];
    const float* Wq = (const float*)d_in[6];
    const float* bq = (const float*)d_in[7];
    const float* Wk = (const float*)d_in[8];
    // d_in[9] = bk: softmax invariant to per-(m,b,h) shift over s -> unused.
    const float* Wv = (const float*)d_in[10];
    const float* bv = (const float*)d_in[11];
    const float* Wo = (const float*)d_in[12];
    const float* bo = (const float*)d_in[13];
    const float* W1  = (const float*)d_in[14];
    const float* b1  = (const float*)d_in[15];
    const float* W2  = (const float*)d_in[16];
    const float* b2  = (const float*)d_in[17];
    const float* Wg1 = (const float*)d_in[18];
    const float* bg1 = (const float*)d_in[19];
    const float* Wg2 = (const float*)d_in[20];
    const float* bg2 = (const float*)d_in[21];
    float* out = (float*)d_out;

    float* scratch = nullptr;
    cudaGetSymbolAddress((void**)&scratch, g_scratch);
    float* q    = scratch;
    float* u    = scratch + 262144;
    float* sc   = scratch + 2359296;
    float* wvb  = scratch + 2883584;
    float* ao   = scratch + 4980736;
    float* x    = scratch + 5242880;
    float* h    = scratch + 5767168;
    float* hg   = scratch + 7864320;
    float* out4 = scratch + 9961472;
    float* gate = scratch + 11010048;

    const float* NOB = nullptr;    // no bias

    // Dynamic smem sizes: 2 * (64*36 + 32*(BN+4)) * 4 bytes
    const int SM128 = 2 * (64 * 36 + 32 * 132) * 4;   // 52224
    const int SM64  = 2 * (64 * 36 + 32 * 68) * 4;    // 35840
    cudaFuncSetAttribute(mma_gemm_kernel<0,false,128>, cudaFuncAttributeMaxDynamicSharedMemorySize, SM128);
    cudaFuncSetAttribute(mma_gemm_kernel<0,true ,128>, cudaFuncAttributeMaxDynamicSharedMemorySize, SM128);
    cudaFuncSetAttribute(mma_gemm_kernel<1,false,128>, cudaFuncAttributeMaxDynamicSharedMemorySize, SM128);
    cudaFuncSetAttribute(mma_gemm_kernel<2,false,128>, cudaFuncAttributeMaxDynamicSharedMemorySize, SM128);
    cudaFuncSetAttribute(mma_gemm_kernel<0,false, 64>, cudaFuncAttributeMaxDynamicSharedMemorySize, SM64);

    // 1) q = prev_query @ Wq + bq          batches m=8
    mma_gemm_kernel<0,false,128><<<dim3(4,8),256,SM128>>>(
        prev_query,512,32768,0,  Wq,512,262144,0,  q,512,32768,0,  bq,512,0,  512,1);

    // 2) u[b][mh][d] = sum_j q[m][b][h64+j] * Wk[m][d][h64+j]   batches (m,h), B K-contig
    mma_gemm_kernel<0,true,128><<<dim3(4,64),256,SM128>>>(
        q,512,32768,64,  Wk,512,262144,64,  u,32768,4096,512,  NOB,0,0,  64,8);

    // 3) scores[b][mh][s] = sum_d u[b][mh][d] * key_in[s][b][d]  batches b, B K-contig
    mma_gemm_kernel<0,true,128><<<dim3(1,64),256,SM128>>>(
        u,512,32768,0,  key_in,32768,512,0,  sc,128,8192,0,  NOB,0,0,  512,1);

    // 4) softmax over s
    softmax128_warp_kernel<<<512,256>>>(sc);

    // 5) wv[b][mh][d] = sum_s w[b][mh][s] * value_in[s][b][d]    batches b
    mma_gemm_kernel<0,false,128><<<dim3(4,64),256,SM128>>>(
        sc,128,8192,0,  value_in,32768,512,0,  wvb,512,32768,0,  NOB,0,0,  128,1);

    // 6) ao[m][b][h64+j] = sum_d wv[b][mh][d]*Wv[m][d][h64+j] + bv   batches (m,h), N=64
    mma_gemm_kernel<0,false,64><<<dim3(1,64),256,SM64>>>(
        wvb,32768,4096,512,  Wv,512,262144,64,  ao,512,32768,64,  bv,512,64,  512,8);

    // 7) x[:, :D] = relu(ao @ Wo + bo)     batches m=8, ldc=1024
    mma_gemm_kernel<1,false,128><<<dim3(4,8),256,SM128>>>(
        ao,512,32768,0,  Wo,512,262144,0,  x,1024,65536,0,  bo,512,0,  512,1);

    // 8) x[:, D:] = relu(prev_state)
    build_x2_kernel<<<1024,256>>>(prev_state, x);

    // 9) h = relu(x @ W1 + b1)             batches (g,m), A = x[m]
    mma_gemm_kernel<1,false,128><<<dim3(8,32),256,SM128>>>(
        x,1024,0,65536,  W1,1024,8388608,1048576,  h,1024,524288,65536,  b1,8192,1024,  1024,8);

    // 10) hg = relu(x @ Wg1 + bg1)
    mma_gemm_kernel<1,false,128><<<dim3(8,32),256,SM128>>>(
        x,1024,0,65536,  Wg1,1024,8388608,1048576,  hg,1024,524288,65536,  bg1,8192,1024,  1024,8);

    // 11) out4 = tanh(relu(h @ W2 + b2))   batches (g,m) linear
    mma_gemm_kernel<2,false,128><<<dim3(4,32),256,SM128>>>(
        h,1024,65536,0,  W2,512,524288,0,  out4,512,32768,0,  b2,512,0,  1024,1);

    // 12) gate = sigmoid(hg @ Wg2 + bg2)
    gate_kernel<<<2048,256>>>(hg, Wg2, bg2, gate);

    // 13) combine + reorder to (state, query, key, value)
    combine_kernel<<<4096,256>>>(out4, gate, prev_query, prev_key, prev_value, prev_state, out);
}

// round 10
// speedup vs baseline: 2.9289x; 1.1796x over previous
#include <cuda_runtime.h>
#include <cuda_bf16.h>
#include <math.h>
#include <stdint.h>

// Problem constants: M=8 modules, B=64 batch, S=128 seq, D=512, H=8 heads (hd=64), FF=1024.

// Scratch (static device array; no runtime allocation).
__device__ float g_scratch[11012096];

__device__ __forceinline__ uint32_t smem_u32(const void* p){
    uint32_t a;
    asm("{ .reg .u64 t; cvta.to.shared.u64 t, %1; cvt.u32.u64 %0, t; }" : "=r"(a) : "l"(p));
    return a;
}
__device__ __forceinline__ void cpasync16(uint32_t dst, const float* src){
    asm volatile("cp.async.cg.shared.global [%0], [%1], 16;" :: "r"(dst), "l"(src) : "memory");
}
__device__ __forceinline__ uint32_t cvt_tf32(float x){
    uint32_t r; asm("cvt.rna.tf32.f32 %0, %1;" : "=r"(r) : "f"(x)); return r;
}

struct EpiArgs {
    const float* wg2;    // EPI1: Wg2 base [4*M][FF]
    float*       gatez;  // EPI1: partial gate sums [8][32][64]
    const float* gzin;   // EPI2: gate partials (read)
    const float* bg2;    // EPI2: [4*M]
    const float* p0; const float* p1; const float* p2; const float* p3;  // prev q,k,v,state
};

// ===========================================================================
// cp.async 3-stage tf32 mma GEMM (NN: W rows n-contiguous).
//   C[64 x N] = act( A[64 x K] @ W[K x N] + bias )  per batch (b1,b0)
// A swizzled in SMEM: element (r,k) at word r*32 + ((k>>2 ^ (r&7))<<2) + (k&3)
//   -> conflict-free m16n8k8 A-fragment loads.
// B stored [k][BN+4].
// EPI: 0 = store C (ACT applied), 1 = gate-partial only (hg=relu(acc+bias),
//      dot with Wg2 cols, deterministic reduction, no C write),
//      2 = final: v=tanh(relu(acc+bias)); gv=sigmoid(sum gz + bg2);
//          out[(g+1)&3][m][b][d] = gv*v + (1-gv)*prev_g[m][b][d]
// ===========================================================================
template<int ACT, int BN, int EPI>
__global__ __launch_bounds__(256) void mma_async_kernel(
    const float* __restrict__ A, int lda, int sA1, int sA0,
    const float* __restrict__ W, int ldw, int sW1, int sW0,
    float* __restrict__ C, int ldc, int sC1, int sC0,
    const float* __restrict__ bias, int sB1, int sB0,
    int K, int inner, EpiArgs epi)
{
    extern __shared__ float smemf[];
    constexpr int A_F = 64 * 32;
    constexpr int BSTR = BN + 4;
    constexpr int B_F = 32 * BSTR;
    constexpr int STAGE_F = A_F + B_F;
    constexpr int BITER = BN / 32;
    constexpr int NA = BN / 32;

    const int tid = threadIdx.x;
    const int wid = tid >> 5, lane = tid & 31;
    const int g = lane >> 2, tig = lane & 3;
    const int warp_m = wid >> 2;
    const int warp_n = wid & 3;
    const int batch = blockIdx.y;
    const int b1 = batch / inner;
    const int b0 = batch - b1 * inner;
    const int n0 = blockIdx.x * BN;

    const float* Ab = A + (size_t)b1 * sA1 + (size_t)b0 * sA0;
    const float* Wb = W + (size_t)b1 * sW1 + (size_t)b0 * sW0 + n0;
    const float* Bb = bias ? bias + (size_t)b1 * sB1 + (size_t)b0 * sB0 + n0 : nullptr;
    float* Cb;
    if (EPI == 2)
        Cb = C + (size_t)(((b1 + 1) & 3)) * 262144 + (size_t)b0 * 32768 + n0;
    else
        Cb = C + (size_t)b1 * sC1 + (size_t)b0 * sC0 + n0;

    const uint32_t sbase = smem_u32(smemf);
    const int NC = K >> 5;

    auto issue = [&](int c){
        const int k0 = c << 5;
        const uint32_t sb = sbase + (uint32_t)(c % 3) * (STAGE_F * 4);
        #pragma unroll
        for (int i = 0; i < 2; i++){
            int f = tid + (i << 8);
            int r = f >> 3, kq = f & 7;
            cpasync16(sb + (uint32_t)(r * 32 + ((kq ^ (r & 7)) << 2)) * 4,
                      Ab + (size_t)r * lda + k0 + (kq << 2));
        }
        #pragma unroll
        for (int i = 0; i < BITER; i++){
            int f = tid + (i << 8);
            int k = f / (BN >> 2), nq = f % (BN >> 2);
            cpasync16(sb + (uint32_t)(A_F + k * BSTR + (nq << 2)) * 4,
                      Wb + (size_t)(k0 + k) * ldw + (nq << 2));
        }
        asm volatile("cp.async.commit_group;" ::: "memory");
    };

    float acc[2][NA][4];
    #pragma unroll
    for (int i = 0; i < 2; i++)
        #pragma unroll
        for (int j = 0; j < NA; j++)
            #pragma unroll
            for (int u = 0; u < 4; u++) acc[i][j][u] = 0.f;

    issue(0);
    issue(1);

    for (int c = 0; c < NC; ++c){
        if (c + 1 < NC) asm volatile("cp.async.wait_group 1;" ::: "memory");
        else            asm volatile("cp.async.wait_group 0;" ::: "memory");
        __syncthreads();
        if (c + 2 < NC) issue(c + 2);

        const uint32_t* Au = reinterpret_cast<const uint32_t*>(smemf + (c % 3) * STAGE_F);
        const uint32_t* Bu = Au + A_F;
        #pragma unroll
        for (int ks = 0; ks < 4; ks++){
            const int kk = ks << 3;
            const int cb = kk >> 2;
            uint32_t af[2][4];
            #pragma unroll
            for (int ma = 0; ma < 2; ma++){
                const int r0 = warp_m * 32 + ma * 16 + g;
                const int r1 = r0 + 8;
                af[ma][0] = Au[r0 * 32 + ((cb ^ g) << 2) + tig];
                af[ma][1] = Au[r1 * 32 + ((cb ^ g) << 2) + tig];
                af[ma][2] = Au[r0 * 32 + (((cb + 1) ^ g) << 2) + tig];
                af[ma][3] = Au[r1 * 32 + (((cb + 1) ^ g) << 2) + tig];
            }
            uint32_t bf[NA][2];
            #pragma unroll
            for (int na = 0; na < NA; na++){
                const int cl = warp_n * (BN / 4) + na * 8 + g;
                bf[na][0] = Bu[(kk + tig) * BSTR + cl];
                bf[na][1] = Bu[(kk + tig + 4) * BSTR + cl];
            }
            #pragma unroll
            for (int ma = 0; ma < 2; ma++)
                #pragma unroll
                for (int na = 0; na < NA; na++){
                    asm volatile(
                        "mma.sync.aligned.m16n8k8.row.col.f32.tf32.tf32.f32 "
                        "{%0,%1,%2,%3}, {%4,%5,%6,%7}, {%8,%9}, {%0,%1,%2,%3};"
                        : "+f"(acc[ma][na][0]), "+f"(acc[ma][na][1]),
                          "+f"(acc[ma][na][2]), "+f"(acc[ma][na][3])
                        : "r"(af[ma][0]), "r"(af[ma][1]), "r"(af[ma][2]), "r"(af[ma][3]),
                          "r"(bf[na][0]), "r"(bf[na][1]));
                }
        }
        __syncthreads();
    }

    if (EPI == 0){
        #pragma unroll
        for (int ma = 0; ma < 2; ma++){
            const int r0 = warp_m * 32 + ma * 16 + g;
            #pragma unroll
            for (int na = 0; na < NA; na++){
                const int cl = warp_n * (BN / 4) + na * 8 + 2 * tig;
                float b0v = Bb ? Bb[cl] : 0.f;
                float b1v = Bb ? Bb[cl + 1] : 0.f;
                float v0 = acc[ma][na][0] + b0v, v1 = acc[ma][na][1] + b1v;
                float v2 = acc[ma][na][2] + b0v, v3 = acc[ma][na][3] + b1v;
                if (ACT >= 1){
                    v0 = fmaxf(v0, 0.f); v1 = fmaxf(v1, 0.f);
                    v2 = fmaxf(v2, 0.f); v3 = fmaxf(v3, 0.f);
                }
                if (ACT == 2){
                    v0 = tanhf(v0); v1 = tanhf(v1); v2 = tanhf(v2); v3 = tanhf(v3);
                }
                *reinterpret_cast<float2*>(Cb + (size_t)r0 * ldc + cl) = make_float2(v0, v1);
                *reinterpret_cast<float2*>(Cb + (size_t)(r0 + 8) * ldc + cl) = make_float2(v2, v3);
            }
        }
    } else if (EPI == 1){
        // hg = relu(acc + bias); partial[row] = sum_cols hg * Wg2[gm][col]
        const float* wg2 = epi.wg2 + (size_t)batch * 1024 + n0;
        float* gbuf = smemf + 3 * STAGE_F;      // [4 warp_n][64 rows]
        float s[2][2];
        #pragma unroll
        for (int ma = 0; ma < 2; ma++){ s[ma][0] = 0.f; s[ma][1] = 0.f; }
        #pragma unroll
        for (int na = 0; na < NA; na++){
            const int cl = warp_n * (BN / 4) + na * 8 + 2 * tig;
            const float b0v = Bb[cl], b1v = Bb[cl + 1];
            const float w0 = wg2[cl], w1 = wg2[cl + 1];
            #pragma unroll
            for (int ma = 0; ma < 2; ma++){
                s[ma][0] += fmaxf(acc[ma][na][0] + b0v, 0.f) * w0
                          + fmaxf(acc[ma][na][1] + b1v, 0.f) * w1;
                s[ma][1] += fmaxf(acc[ma][na][2] + b0v, 0.f) * w0
                          + fmaxf(acc[ma][na][3] + b1v, 0.f) * w1;
            }
        }
        #pragma unroll
        for (int ma = 0; ma < 2; ma++)
            #pragma unroll
            for (int hh = 0; hh < 2; hh++){
                s[ma][hh] += __shfl_xor_sync(0xffffffffu, s[ma][hh], 1);
                s[ma][hh] += __shfl_xor_sync(0xffffffffu, s[ma][hh], 2);
            }
        if (tig == 0){
            #pragma unroll
            for (int ma = 0; ma < 2; ma++){
                gbuf[warp_n * 64 + warp_m * 32 + ma * 16 + g]     = s[ma][0];
                gbuf[warp_n * 64 + warp_m * 32 + ma * 16 + g + 8] = s[ma][1];
            }
        }
        __syncthreads();
        if (tid < 64){
            float p = gbuf[tid] + gbuf[64 + tid] + gbuf[128 + tid] + gbuf[192 + tid];
            epi.gatez[((size_t)blockIdx.x * 32 + batch) * 64 + tid] = p;
        }
    } else {   // EPI == 2: final combine
        const float bg2v = epi.bg2[batch];
        const float* prev;
        if      (b1 == 0) prev = epi.p0;
        else if (b1 == 1) prev = epi.p1;
        else if (b1 == 2) prev = epi.p2;
        else              prev = epi.p3;
        prev += (size_t)b0 * 32768 + n0;
        #pragma unroll
        for (int ma = 0; ma < 2; ma++){
            const int r0 = warp_m * 32 + ma * 16 + g;
            const int r1 = r0 + 8;
            float gz0 = 0.f, gz1 = 0.f;
            #pragma unroll
            for (int i = 0; i < 8; i++){
                gz0 += epi.gzin[((size_t)i * 32 + batch) * 64 + r0];
                gz1 += epi.gzin[((size_t)i * 32 + batch) * 64 + r1];
            }
            const float gv0 = 1.f / (1.f + __expf(-(gz0 + bg2v)));
            const float gv1 = 1.f / (1.f + __expf(-(gz1 + bg2v)));
            #pragma unroll
            for (int na = 0; na < NA; na++){
                const int cl = warp_n * (BN / 4) + na * 8 + 2 * tig;
                const float b0v = Bb[cl], b1v = Bb[cl + 1];
                float v0 = tanhf(fmaxf(acc[ma][na][0] + b0v, 0.f));
                float v1 = tanhf(fmaxf(acc[ma][na][1] + b1v, 0.f));
                float v2 = tanhf(fmaxf(acc[ma][na][2] + b0v, 0.f));
                float v3 = tanhf(fmaxf(acc[ma][na][3] + b1v, 0.f));
                float2 pA = *reinterpret_cast<const float2*>(prev + (size_t)r0 * 512 + cl);
                float2 pB = *reinterpret_cast<const float2*>(prev + (size_t)r1 * 512 + cl);
                float2 o0 = make_float2(gv0 * v0 + (1.f - gv0) * pA.x,
                                        gv0 * v1 + (1.f - gv0) * pA.y);
                float2 o1 = make_float2(gv1 * v2 + (1.f - gv1) * pB.x,
                                        gv1 * v3 + (1.f - gv1) * pB.y);
                *reinterpret_cast<float2*>(Cb + (size_t)r0 * 512 + cl) = o0;
                *reinterpret_cast<float2*>(Cb + (size_t)r1 * 512 + cl) = o1;
            }
        }
    }
}

// ===========================================================================
// LDG+cvt double-buffered tf32 GEMM for NT shapes (B K-contiguous): steps 2,3.
// ===========================================================================
template<int ACT, bool BNT, int BN>
__global__ __launch_bounds__(256) void mma_gemm_kernel(
    const float* __restrict__ A, int lda, int sA1, int sA0,
    const float* __restrict__ W, int ldw, int sW1, int sW0,
    float* __restrict__ C, int ldc, int sC1, int sC0,
    const float* __restrict__ bias, int sB1, int sB0,
    int K, int inner)
{
    extern __shared__ float smemf[];
    constexpr int A_F = 64 * 36;
    constexpr int BSTR = BN + 4;
    constexpr int STAGE_F = A_F + 32 * BSTR;

    const int tid = threadIdx.x;
    const int wid = tid >> 5, lane = tid & 31;
    const int g = lane >> 2, tig = lane & 3;
    const int warp_m = wid >> 2;
    const int warp_n = wid & 3;
    const int batch = blockIdx.y;
    const int b1 = batch / inner;
    const int b0 = batch - b1 * inner;
    const int n0 = blockIdx.x * BN;

    const float* Ab = A + (size_t)b1 * sA1 + (size_t)b0 * sA0;
    const float* Wb = W + (size_t)b1 * sW1 + (size_t)b0 * sW0
                        + (BNT ? (size_t)n0 * ldw : (size_t)n0);
    float*       Cb = C + (size_t)b1 * sC1 + (size_t)b0 * sC0 + n0;
    const float* Bb = bias ? bias + (size_t)b1 * sB1 + (size_t)b0 * sB0 + n0 : nullptr;

    const int NC = K >> 5;
    constexpr int BITER = BN / 32;

    float4 aR[2], bR[BITER];
    auto ldg = [&](int c){
        const int k0 = c << 5;
        #pragma unroll
        for (int i = 0; i < 2; i++){
            int f = tid + (i << 8);
            int r = f >> 3, kq = f & 7;
            aR[i] = *reinterpret_cast<const float4*>(Ab + (size_t)r * lda + k0 + (kq << 2));
        }
        #pragma unroll
        for (int i = 0; i < BITER; i++){
            int f = tid + (i << 8);
            if (BNT){
                int n = f >> 3, kq = f & 7;
                bR[i] = *reinterpret_cast<const float4*>(Wb + (size_t)n * ldw + k0 + (kq << 2));
            } else {
                int k = f / (BN >> 2), nq = f % (BN >> 2);
                bR[i] = *reinterpret_cast<const float4*>(Wb + (size_t)(k0 + k) * ldw + (nq << 2));
            }
        }
    };
    auto sts = [&](int s){
        uint32_t* Au = reinterpret_cast<uint32_t*>(smemf + s * STAGE_F);
        uint32_t* Bu = reinterpret_cast<uint32_t*>(smemf + s * STAGE_F + A_F);
        #pragma unroll
        for (int i = 0; i < 2; i++){
            int f = tid + (i << 8);
            int r = f >> 3, kq = f & 7;
            uint4 v = make_uint4(cvt_tf32(aR[i].x), cvt_tf32(aR[i].y),
                                 cvt_tf32(aR[i].z), cvt_tf32(aR[i].w));
            *reinterpret_cast<uint4*>(&Au[r * 36 + (kq << 2)]) = v;
        }
        #pragma unroll
        for (int i = 0; i < BITER; i++){
            int f = tid + (i << 8);
            if (BNT){
                int n = f >> 3, kq = f & 7;
                Bu[(4 * kq + 0) * BSTR + n] = cvt_tf32(bR[i].x);
                Bu[(4 * kq + 1) * BSTR + n] = cvt_tf32(bR[i].y);
                Bu[(4 * kq + 2) * BSTR + n] = cvt_tf32(bR[i].z);
                Bu[(4 * kq + 3) * BSTR + n] = cvt_tf32(bR[i].w);
            } else {
                int k = f / (BN >> 2), nq = f % (BN >> 2);
                uint4 v = make_uint4(cvt_tf32(bR[i].x), cvt_tf32(bR[i].y),
                                     cvt_tf32(bR[i].z), cvt_tf32(bR[i].w));
                *reinterpret_cast<uint4*>(&Bu[k * BSTR + (nq << 2)]) = v;
            }
        }
    };

    constexpr int NA = BN / 32;
    float acc[2][NA][4];
    #pragma unroll
    for (int i = 0; i < 2; i++)
        #pragma unroll
        for (int j = 0; j < NA; j++)
            #pragma unroll
            for (int u = 0; u < 4; u++) acc[i][j][u] = 0.f;

    ldg(0);
    sts(0);
    if (NC > 1) ldg(1);
    __syncthreads();

    for (int c = 0; c < NC; ++c){
        const int s = c & 1;
        if (c + 1 < NC){
            sts(s ^ 1);
            if (c + 2 < NC) ldg(c + 2);
        }
        const uint32_t* Au = reinterpret_cast<const uint32_t*>(smemf + s * STAGE_F);
        const uint32_t* Bu = reinterpret_cast<const uint32_t*>(smemf + s * STAGE_F + A_F);
        #pragma unroll
        for (int ks = 0; ks < 4; ks++){
            const int kk = ks << 3;
            uint32_t af[2][4];
            #pragma unroll
            for (int ma = 0; ma < 2; ma++){
                const int r0 = warp_m * 32 + ma * 16 + g;
                af[ma][0] = Au[r0 * 36 + kk + tig];
                af[ma][1] = Au[(r0 + 8) * 36 + kk + tig];
                af[ma][2] = Au[r0 * 36 + kk + tig + 4];
                af[ma][3] = Au[(r0 + 8) * 36 + kk + tig + 4];
            }
            uint32_t bf[NA][2];
            #pragma unroll
            for (int na = 0; na < NA; na++){
                const int cl = warp_n * (BN / 4) + na * 8 + g;
                bf[na][0] = Bu[(kk + tig) * BSTR + cl];
                bf[na][1] = Bu[(kk + tig + 4) * BSTR + cl];
            }
            #pragma unroll
            for (int ma = 0; ma < 2; ma++)
                #pragma unroll
                for (int na = 0; na < NA; na++){
                    asm volatile(
                        "mma.sync.aligned.m16n8k8.row.col.f32.tf32.tf32.f32 "
                        "{%0,%1,%2,%3}, {%4,%5,%6,%7}, {%8,%9}, {%0,%1,%2,%3};"
                        : "+f"(acc[ma][na][0]), "+f"(acc[ma][na][1]),
                          "+f"(acc[ma][na][2]), "+f"(acc[ma][na][3])
                        : "r"(af[ma][0]), "r"(af[ma][1]), "r"(af[ma][2]), "r"(af[ma][3]),
                          "r"(bf[na][0]), "r"(bf[na][1]));
                }
        }
        __syncthreads();
    }

    #pragma unroll
    for (int ma = 0; ma < 2; ma++){
        const int r0 = warp_m * 32 + ma * 16 + g;
        #pragma unroll
        for (int na = 0; na < NA; na++){
            const int cl = warp_n * (BN / 4) + na * 8 + 2 * tig;
            float b0v = Bb ? Bb[cl] : 0.f;
            float b1v = Bb ? Bb[cl + 1] : 0.f;
            float v0 = acc[ma][na][0] + b0v, v1 = acc[ma][na][1] + b1v;
            float v2 = acc[ma][na][2] + b0v, v3 = acc[ma][na][3] + b1v;
            if (ACT >= 1){
                v0 = fmaxf(v0, 0.f); v1 = fmaxf(v1, 0.f);
                v2 = fmaxf(v2, 0.f); v3 = fmaxf(v3, 0.f);
            }
            if (ACT == 2){
                v0 = tanhf(v0); v1 = tanhf(v1); v2 = tanhf(v2); v3 = tanhf(v3);
            }
            *reinterpret_cast<float2*>(Cb + (size_t)r0 * ldc + cl) = make_float2(v0, v1);
            *reinterpret_cast<float2*>(Cb + (size_t)(r0 + 8) * ldc + cl) = make_float2(v2, v3);
        }
    }
}

// Warp-per-row softmax over S=128 (4096 rows); includes 1/sqrt(hd)=0.125 scale.
__global__ __launch_bounds__(256) void softmax128_warp_kernel(float* __restrict__ p)
{
    const int row = blockIdx.x * 8 + (threadIdx.x >> 5);
    const int lane = threadIdx.x & 31;
    float4* r4 = reinterpret_cast<float4*>(p + (size_t)row * 128) + lane;
    float4 v = *r4;
    v.x *= 0.125f; v.y *= 0.125f; v.z *= 0.125f; v.w *= 0.125f;
    float mx = fmaxf(fmaxf(v.x, v.y), fmaxf(v.z, v.w));
    #pragma unroll
    for (int o = 16; o > 0; o >>= 1) mx = fmaxf(mx, __shfl_xor_sync(0xffffffffu, mx, o));
    float e0 = __expf(v.x - mx), e1 = __expf(v.y - mx);
    float e2 = __expf(v.z - mx), e3 = __expf(v.w - mx);
    float sm = e0 + e1 + e2 + e3;
    #pragma unroll
    for (int o = 16; o > 0; o >>= 1) sm += __shfl_xor_sync(0xffffffffu, sm, o);
    const float inv = 1.f / sm;
    *r4 = make_float4(e0 * inv, e1 * inv, e2 * inv, e3 * inv);
}

// x[m][b][D + d] = relu(prev_state[m][b][d])
__global__ __launch_bounds__(256) void build_x2_kernel(const float* __restrict__ ps,
                                                       float* __restrict__ x)
{
    int idx = blockIdx.x * 256 + threadIdx.x;
    int m = idx >> 15;
    int rem = idx & 32767;
    int b = rem >> 9;
    int d = rem & 511;
    x[(size_t)m * 65536 + b * 1024 + 512 + d] = fmaxf(ps[idx], 0.f);
}

extern "C" void kernel_launch(void* const* d_in, const int* in_sizes, int n_in,
                              void* d_out, int out_size)
{
    (void)in_sizes; (void)n_in; (void)out_size;
    const float* prev_state = (const float*)d_in[0];
    const float* prev_query = (const float*)d_in[1];
    const float* prev_key   = (const float*)d_in[2];
    const float* prev_value = (const float*)d_in[3];
    const float* key_in     = (const float*)d_in[4];
    const float* value_in   = (const float*)d_in[5];
    const float* Wq = (const float*)d_in[6];
    const float* bq = (const float*)d_in[7];
    const float* Wk = (const float*)d_in[8];
    // d_in[9] = bk: softmax invariant to per-(m,b,h) shift over s -> unused.
    const float* Wv = (const float*)d_in[10];
    const float* bv = (const float*)d_in[11];
    const float* Wo = (const float*)d_in[12];
    const float* bo = (const float*)d_in[13];
    const float* W1  = (const float*)d_in[14];
    const float* b1  = (const float*)d_in[15];
    const float* W2  = (const float*)d_in[16];
    const float* b2  = (const float*)d_in[17];
    const float* Wg1 = (const float*)d_in[18];
    const float* bg1 = (const float*)d_in[19];
    const float* Wg2 = (const float*)d_in[20];
    const float* bg2 = (const float*)d_in[21];
    float* out = (float*)d_out;

    float* scratch = nullptr;
    cudaGetSymbolAddress((void**)&scratch, g_scratch);
    float* q     = scratch;
    float* u     = scratch + 262144;
    float* sc    = scratch + 2359296;
    float* wvb   = scratch + 2883584;
    float* ao    = scratch + 4980736;
    float* x     = scratch + 5242880;
    float* h     = scratch + 5767168;
    float* gatez = scratch + 7864320;   // [8][32][64] = 16384 floats

    const float* NOB = nullptr;
    EpiArgs E0{};   // unused-aux default

    // smem sizes
    const int ASM128 = (3 * (64 * 32 + 32 * 132) + 256) * 4;   // 76288
    const int ASM64  = (3 * (64 * 32 + 32 * 68) + 256) * 4;    // 51712
    const int NTSM128 = 2 * (64 * 36 + 32 * 132) * 4;          // 52224
    const int NTSM64  = 2 * (64 * 36 + 32 * 68) * 4;           // 35840
    cudaFuncSetAttribute(mma_async_kernel<0,128,0>, cudaFuncAttributeMaxDynamicSharedMemorySize, ASM128);
    cudaFuncSetAttribute(mma_async_kernel<1,128,0>, cudaFuncAttributeMaxDynamicSharedMemorySize, ASM128);
    cudaFuncSetAttribute(mma_async_kernel<0, 64,0>, cudaFuncAttributeMaxDynamicSharedMemorySize, ASM64);
    cudaFuncSetAttribute(mma_async_kernel<1,128,1>, cudaFuncAttributeMaxDynamicSharedMemorySize, ASM128);
    cudaFuncSetAttribute(mma_async_kernel<2,128,2>, cudaFuncAttributeMaxDynamicSharedMemorySize, ASM128);
    cudaFuncSetAttribute(mma_gemm_kernel<0,true,128>, cudaFuncAttributeMaxDynamicSharedMemorySize, NTSM128);
    cudaFuncSetAttribute(mma_gemm_kernel<0,true, 64>, cudaFuncAttributeMaxDynamicSharedMemorySize, NTSM64);

    // 1) q = prev_query @ Wq + bq          batches m
    mma_async_kernel<0,128,0><<<dim3(4,8),256,ASM128>>>(
        prev_query,512,32768,0,  Wq,512,262144,0,  q,512,32768,0,  bq,512,0,  512,1, E0);

    // 2) u[b][mh][d] = sum_j q[m][b][h64+j] * Wk[m][d][h64+j]   batches (m,h), NT
    mma_gemm_kernel<0,true,128><<<dim3(4,64),256,NTSM128>>>(
        q,512,32768,64,  Wk,512,262144,64,  u,32768,4096,512,  NOB,0,0,  64,8);

    // 3) scores[b][mh][s] = sum_d u[b][mh][d] * key_in[s][b][d]  batches b, NT, BN=64
    mma_gemm_kernel<0,true,64><<<dim3(2,64),256,NTSM64>>>(
        u,512,32768,0,  key_in,32768,512,0,  sc,128,8192,0,  NOB,0,0,  512,1);

    // 4) softmax over s
    softmax128_warp_kernel<<<512,256>>>(sc);

    // 5) wv[b][mh][d] = sum_s w[b][mh][s] * value_in[s][b][d]    batches b
    mma_async_kernel<0,128,0><<<dim3(4,64),256,ASM128>>>(
        sc,128,8192,0,  value_in,32768,512,0,  wvb,512,32768,0,  NOB,0,0,  128,1, E0);

    // 6) ao[m][b][h64+j] = sum_d wv[b][mh][d]*Wv[m][d][h64+j] + bv   batches (m,h), BN=64
    mma_async_kernel<0,64,0><<<dim3(1,64),256,ASM64>>>(
        wvb,32768,4096,512,  Wv,512,262144,64,  ao,512,32768,64,  bv,512,64,  512,8, E0);

    // 7) x[:, :D] = relu(ao @ Wo + bo)     batches m, ldc=1024
    mma_async_kernel<1,128,0><<<dim3(4,8),256,ASM128>>>(
        ao,512,32768,0,  Wo,512,262144,0,  x,1024,65536,0,  bo,512,0,  512,1, E0);

    // 8) x[:, D:] = relu(prev_state)
    build_x2_kernel<<<1024,256>>>(prev_state, x);

    // 9) h = relu(x @ W1 + b1)             batches (g,m)
    mma_async_kernel<1,128,0><<<dim3(8,32),256,ASM128>>>(
        x,1024,0,65536,  W1,1024,8388608,1048576,  h,1024,524288,65536,  b1,8192,1024,  1024,8, E0);

    // 10) gate partials: hg = relu(x @ Wg1 + bg1); gatez[cta][gm][b] = sum hg*Wg2
    {
        EpiArgs E1{};
        E1.wg2 = Wg2; E1.gatez = gatez;
        mma_async_kernel<1,128,1><<<dim3(8,32),256,ASM128>>>(
            x,1024,0,65536,  Wg1,1024,8388608,1048576,  nullptr,0,0,0,  bg1,8192,1024,  1024,8, E1);
    }

    // 11) final: v=tanh(relu(h@W2+b2)); gv=sigmoid(sum gatez + bg2);
    //     out[(g+1)&3][m][b][d] = gv*v + (1-gv)*prev_g
    //     A = h[g][m]: strides (524288, 65536)  <-- R9 bug was (65536, 0)
    {
        EpiArgs E2{};
        E2.gzin = gatez; E2.bg2 = bg2;
        E2.p0 = prev_query; E2.p1 = prev_key; E2.p2 = prev_value; E2.p3 = prev_state;
        mma_async_kernel<2,128,2><<<dim3(4,32),256,ASM128>>>(
            h,1024,524288,65536,  W2,512,4194304,524288,  out,512,0,0,  b2,4096,512,  1024,8, E2);
    }
}

// round 11
// speedup vs baseline: 3.0020x; 1.0250x over previous
#include <cuda_runtime.h>
#include <cuda_bf16.h>
#include <math.h>
#include <stdint.h>

// Problem constants: M=8 modules, B=64 batch, S=128 seq, D=512, H=8 heads (hd=64), FF=1024.

// Scratch (static device array; no runtime allocation).
__device__ float g_scratch[11012096];

__device__ __forceinline__ uint32_t smem_u32(const void* p){
    uint32_t a;
    asm("{ .reg .u64 t; cvta.to.shared.u64 t, %1; cvt.u32.u64 %0, t; }" : "=r"(a) : "l"(p));
    return a;
}
__device__ __forceinline__ void cpasync16(uint32_t dst, const float* src){
    asm volatile("cp.async.cg.shared.global [%0], [%1], 16;" :: "r"(dst), "l"(src) : "memory");
}
__device__ __forceinline__ uint32_t cvt_tf32(float x){
    uint32_t r; asm("cvt.rna.tf32.f32 %0, %1;" : "=r"(r) : "f"(x)); return r;
}
#define MMA_TF32(acc, af, bf) \
    asm volatile( \
        "mma.sync.aligned.m16n8k8.row.col.f32.tf32.tf32.f32 " \
        "{%0,%1,%2,%3}, {%4,%5,%6,%7}, {%8,%9}, {%0,%1,%2,%3};" \
        : "+f"((acc)[0]), "+f"((acc)[1]), "+f"((acc)[2]), "+f"((acc)[3]) \
        : "r"((af)[0]), "r"((af)[1]), "r"((af)[2]), "r"((af)[3]), \
          "r"((bf)[0]), "r"((bf)[1]))

struct EpiArgs {
    const float* wg2;    // gate: Wg2 base [4*M][FF]
    float*       gatez;  // gate: partial sums [8][32][64]
    const float* gzin;   // EPI2: gate partials (read)
    const float* bg2;    // EPI2: [4*M]
    const float* p0; const float* p1; const float* p2; const float* p3;  // prev q,k,v,state
    const float* wAlt;   // EPI3: Wg1
    const float* bAlt;   // EPI3: bg1
};

// ===========================================================================
// cp.async 3-stage tf32 mma GEMM (NN: W rows n-contiguous).
//   C[64 x N] = act( A[64 x K] @ W[K x N] + bias )  per batch (b1,b0)
// A swizzled in SMEM: (r,k) at word r*32 + ((k>>2 ^ (r&7))<<2) + (k&3).
// EPI: 0 = store C
//      2 = final combine (tanh/gate/prev-mix, writes d_out)
//      3 = dual MLP: blockIdx.x<8 -> store C (h, W/bias); >=8 -> gate partial
//          (W=wAlt, bias=bAlt, dot with wg2 -> gatez[nx])
//      4 = store C + also x[:,512+n] = relu(prev_state)  (concat fold-in)
// ===========================================================================
template<int ACT, int BN, int EPI>
__global__ __launch_bounds__(256) void mma_async_kernel(
    const float* __restrict__ A, int lda, int sA1, int sA0,
    const float* __restrict__ W, int ldw, int sW1, int sW0,
    float* __restrict__ C, int ldc, int sC1, int sC0,
    const float* __restrict__ bias, int sB1, int sB0,
    int K, int inner, EpiArgs epi)
{
    extern __shared__ float smemf[];
    constexpr int A_F = 64 * 32;
    constexpr int BSTR = BN + 4;
    constexpr int B_F = 32 * BSTR;
    constexpr int STAGE_F = A_F + B_F;
    constexpr int BITER = BN / 32;
    constexpr int NA = BN / 32;

    const int tid = threadIdx.x;
    const int wid = tid >> 5, lane = tid & 31;
    const int g = lane >> 2, tig = lane & 3;
    const int warp_m = wid >> 2;
    const int warp_n = wid & 3;
    const int batch = blockIdx.y;
    const int b1 = batch / inner;
    const int b0 = batch - b1 * inner;
    const int nx = (EPI == 3) ? (blockIdx.x & 7) : blockIdx.x;
    const int n0 = nx * BN;
    const bool gp = (EPI == 3) && (blockIdx.x >= 8);

    const float* Wsel = gp ? epi.wAlt : W;
    const float* Bsel = gp ? epi.bAlt : bias;

    const float* Ab = A + (size_t)b1 * sA1 + (size_t)b0 * sA0;
    const float* Wb = Wsel + (size_t)b1 * sW1 + (size_t)b0 * sW0 + n0;
    const float* Bb = Bsel ? Bsel + (size_t)b1 * sB1 + (size_t)b0 * sB0 + n0 : nullptr;
    float* Cb;
    if (EPI == 2)
        Cb = C + (size_t)(((b1 + 1) & 3)) * 262144 + (size_t)b0 * 32768 + n0;
    else
        Cb = C + (size_t)b1 * sC1 + (size_t)b0 * sC0 + n0;

    const uint32_t sbase = smem_u32(smemf);
    const int NC = K >> 5;

    auto issue = [&](int c){
        const int k0 = c << 5;
        const uint32_t sb = sbase + (uint32_t)(c % 3) * (STAGE_F * 4);
        #pragma unroll
        for (int i = 0; i < 2; i++){
            int f = tid + (i << 8);
            int r = f >> 3, kq = f & 7;
            cpasync16(sb + (uint32_t)(r * 32 + ((kq ^ (r & 7)) << 2)) * 4,
                      Ab + (size_t)r * lda + k0 + (kq << 2));
        }
        #pragma unroll
        for (int i = 0; i < BITER; i++){
            int f = tid + (i << 8);
            int k = f / (BN >> 2), nq = f % (BN >> 2);
            cpasync16(sb + (uint32_t)(A_F + k * BSTR + (nq << 2)) * 4,
                      Wb + (size_t)(k0 + k) * ldw + (nq << 2));
        }
        asm volatile("cp.async.commit_group;" ::: "memory");
    };

    float acc[2][NA][4];
    #pragma unroll
    for (int i = 0; i < 2; i++)
        #pragma unroll
        for (int j = 0; j < NA; j++)
            #pragma unroll
            for (int u = 0; u < 4; u++) acc[i][j][u] = 0.f;

    issue(0);
    issue(1);

    for (int c = 0; c < NC; ++c){
        if (c + 1 < NC) asm volatile("cp.async.wait_group 1;" ::: "memory");
        else            asm volatile("cp.async.wait_group 0;" ::: "memory");
        __syncthreads();
        if (c + 2 < NC) issue(c + 2);

        const uint32_t* Au = reinterpret_cast<const uint32_t*>(smemf + (c % 3) * STAGE_F);
        const uint32_t* Bu = Au + A_F;
        #pragma unroll
        for (int ks = 0; ks < 4; ks++){
            const int kk = ks << 3;
            const int cb = kk >> 2;
            uint32_t af[2][4];
            #pragma unroll
            for (int ma = 0; ma < 2; ma++){
                const int r0 = warp_m * 32 + ma * 16 + g;
                const int r1 = r0 + 8;
                af[ma][0] = Au[r0 * 32 + ((cb ^ g) << 2) + tig];
                af[ma][1] = Au[r1 * 32 + ((cb ^ g) << 2) + tig];
                af[ma][2] = Au[r0 * 32 + (((cb + 1) ^ g) << 2) + tig];
                af[ma][3] = Au[r1 * 32 + (((cb + 1) ^ g) << 2) + tig];
            }
            uint32_t bf[NA][2];
            #pragma unroll
            for (int na = 0; na < NA; na++){
                const int cl = warp_n * (BN / 4) + na * 8 + g;
                bf[na][0] = Bu[(kk + tig) * BSTR + cl];
                bf[na][1] = Bu[(kk + tig + 4) * BSTR + cl];
            }
            #pragma unroll
            for (int ma = 0; ma < 2; ma++)
                #pragma unroll
                for (int na = 0; na < NA; na++)
                    MMA_TF32(acc[ma][na], af[ma], bf[na]);
        }
        __syncthreads();
    }

    if (EPI == 0 || EPI == 4 || (EPI == 3 && !gp)){
        #pragma unroll
        for (int ma = 0; ma < 2; ma++){
            const int r0 = warp_m * 32 + ma * 16 + g;
            #pragma unroll
            for (int na = 0; na < NA; na++){
                const int cl = warp_n * (BN / 4) + na * 8 + 2 * tig;
                float b0v = Bb ? Bb[cl] : 0.f;
                float b1v = Bb ? Bb[cl + 1] : 0.f;
                float v0 = acc[ma][na][0] + b0v, v1 = acc[ma][na][1] + b1v;
                float v2 = acc[ma][na][2] + b0v, v3 = acc[ma][na][3] + b1v;
                if (ACT >= 1){
                    v0 = fmaxf(v0, 0.f); v1 = fmaxf(v1, 0.f);
                    v2 = fmaxf(v2, 0.f); v3 = fmaxf(v3, 0.f);
                }
                if (ACT == 2){
                    v0 = tanhf(v0); v1 = tanhf(v1); v2 = tanhf(v2); v3 = tanhf(v3);
                }
                *reinterpret_cast<float2*>(Cb + (size_t)r0 * ldc + cl) = make_float2(v0, v1);
                *reinterpret_cast<float2*>(Cb + (size_t)(r0 + 8) * ldc + cl) = make_float2(v2, v3);
            }
        }
        if (EPI == 4){
            // fold-in: x[m][b][512 + n0 + cl] = relu(prev_state[m][b][n0 + cl])
            const float* ps = epi.p3 + (size_t)b1 * 32768 + n0;
            #pragma unroll
            for (int ma = 0; ma < 2; ma++){
                const int r0 = warp_m * 32 + ma * 16 + g;
                #pragma unroll
                for (int na = 0; na < NA; na++){
                    const int cl = warp_n * (BN / 4) + na * 8 + 2 * tig;
                    float2 pv0 = *reinterpret_cast<const float2*>(ps + (size_t)r0 * 512 + cl);
                    float2 pv1 = *reinterpret_cast<const float2*>(ps + (size_t)(r0 + 8) * 512 + cl);
                    *reinterpret_cast<float2*>(Cb + 512 + (size_t)r0 * ldc + cl) =
                        make_float2(fmaxf(pv0.x, 0.f), fmaxf(pv0.y, 0.f));
                    *reinterpret_cast<float2*>(Cb + 512 + (size_t)(r0 + 8) * ldc + cl) =
                        make_float2(fmaxf(pv1.x, 0.f), fmaxf(pv1.y, 0.f));
                }
            }
        }
    } else if (EPI == 3){   // gate partial path
        const float* wg2 = epi.wg2 + (size_t)batch * 1024 + n0;
        float* gbuf = smemf + 3 * STAGE_F;      // [4 warp_n][64 rows]
        float s[2][2];
        #pragma unroll
        for (int ma = 0; ma < 2; ma++){ s[ma][0] = 0.f; s[ma][1] = 0.f; }
        #pragma unroll
        for (int na = 0; na < NA; na++){
            const int cl = warp_n * (BN / 4) + na * 8 + 2 * tig;
            const float b0v = Bb[cl], b1v = Bb[cl + 1];
            const float w0 = wg2[cl], w1 = wg2[cl + 1];
            #pragma unroll
            for (int ma = 0; ma < 2; ma++){
                s[ma][0] += fmaxf(acc[ma][na][0] + b0v, 0.f) * w0
                          + fmaxf(acc[ma][na][1] + b1v, 0.f) * w1;
                s[ma][1] += fmaxf(acc[ma][na][2] + b0v, 0.f) * w0
                          + fmaxf(acc[ma][na][3] + b1v, 0.f) * w1;
            }
        }
        #pragma unroll
        for (int ma = 0; ma < 2; ma++)
            #pragma unroll
            for (int hh = 0; hh < 2; hh++){
                s[ma][hh] += __shfl_xor_sync(0xffffffffu, s[ma][hh], 1);
                s[ma][hh] += __shfl_xor_sync(0xffffffffu, s[ma][hh], 2);
            }
        if (tig == 0){
            #pragma unroll
            for (int ma = 0; ma < 2; ma++){
                gbuf[warp_n * 64 + warp_m * 32 + ma * 16 + g]     = s[ma][0];
                gbuf[warp_n * 64 + warp_m * 32 + ma * 16 + g + 8] = s[ma][1];
            }
        }
        __syncthreads();
        if (tid < 64){
            float p = gbuf[tid] + gbuf[64 + tid] + gbuf[128 + tid] + gbuf[192 + tid];
            epi.gatez[((size_t)nx * 32 + batch) * 64 + tid] = p;
        }
    } else if (EPI == 2){   // final combine
        const float bg2v = epi.bg2[batch];
        const float* prev;
        if      (b1 == 0) prev = epi.p0;
        else if (b1 == 1) prev = epi.p1;
        else if (b1 == 2) prev = epi.p2;
        else              prev = epi.p3;
        prev += (size_t)b0 * 32768 + n0;
        #pragma unroll
        for (int ma = 0; ma < 2; ma++){
            const int r0 = warp_m * 32 + ma * 16 + g;
            const int r1 = r0 + 8;
            float gz0 = 0.f, gz1 = 0.f;
            #pragma unroll
            for (int i = 0; i < 8; i++){
                gz0 += epi.gzin[((size_t)i * 32 + batch) * 64 + r0];
                gz1 += epi.gzin[((size_t)i * 32 + batch) * 64 + r1];
            }
            const float gv0 = 1.f / (1.f + __expf(-(gz0 + bg2v)));
            const float gv1 = 1.f / (1.f + __expf(-(gz1 + bg2v)));
            #pragma unroll
            for (int na = 0; na < NA; na++){
                const int cl = warp_n * (BN / 4) + na * 8 + 2 * tig;
                const float b0v = Bb[cl], b1v = Bb[cl + 1];
                float v0 = tanhf(fmaxf(acc[ma][na][0] + b0v, 0.f));
                float v1 = tanhf(fmaxf(acc[ma][na][1] + b1v, 0.f));
                float v2 = tanhf(fmaxf(acc[ma][na][2] + b0v, 0.f));
                float v3 = tanhf(fmaxf(acc[ma][na][3] + b1v, 0.f));
                float2 pA = *reinterpret_cast<const float2*>(prev + (size_t)r0 * 512 + cl);
                float2 pB = *reinterpret_cast<const float2*>(prev + (size_t)r1 * 512 + cl);
                float2 o0 = make_float2(gv0 * v0 + (1.f - gv0) * pA.x,
                                        gv0 * v1 + (1.f - gv0) * pA.y);
                float2 o1 = make_float2(gv1 * v2 + (1.f - gv1) * pB.x,
                                        gv1 * v3 + (1.f - gv1) * pB.y);
                *reinterpret_cast<float2*>(Cb + (size_t)r0 * 512 + cl) = o0;
                *reinterpret_cast<float2*>(Cb + (size_t)r1 * 512 + cl) = o1;
            }
        }
    }
}

// ===========================================================================
// Fused attention core (steps 3+4+5), one CTA per batch b (grid 64):
//   scores[mh][s] = (u[b] @ key_in[:,b,:]^T) * 0.125   (K=512)
//   w = softmax_s(scores)                              (in-register + smem red)
//   wv[b][mh][d] = w @ value_in[:,b,:]                 (K=128, N=512)
// ===========================================================================
__global__ __launch_bounds__(256) void fused_attn_kernel(
    const float* __restrict__ u, const float* __restrict__ key_in,
    const float* __restrict__ value_in, float* __restrict__ wvb)
{
    extern __shared__ float smemf[];
    constexpr int A_W  = 2048;            // 64x32 swizzled A
    constexpr int B_W  = 4224;            // max(128x32 swz-NT, 32x132 NN)
    constexpr int STG  = A_W + B_W;       // 6272
    constexpr int WBUF = 3 * STG;         // softmaxed w, 4 chunks of 64x32
    constexpr int RED  = WBUF + 8192;     // [4][64] reduction buffer

    const int tid = threadIdx.x;
    const int wid = tid >> 5, lane = tid & 31;
    const int g = lane >> 2, tig = lane & 3;
    const int warp_m = wid >> 2, warp_n = wid & 3;
    const int b = blockIdx.x;
    const uint32_t sbase = smem_u32(smemf);

    // ---------------- phase 1: scores ----------------
    auto issue1 = [&](int c){
        const int k0 = c << 5;
        const uint32_t sb = sbase + (uint32_t)(c % 3) * (STG * 4);
        #pragma unroll
        for (int i = 0; i < 2; i++){
            int f = tid + (i << 8); int r = f >> 3, kq = f & 7;
            cpasync16(sb + (uint32_t)(r * 32 + ((kq ^ (r & 7)) << 2)) * 4,
                      u + (size_t)b * 32768 + (size_t)r * 512 + k0 + (kq << 2));
        }
        #pragma unroll
        for (int i = 0; i < 4; i++){
            int f = tid + (i << 8); int n = f >> 3, kq = f & 7;
            cpasync16(sb + (uint32_t)(A_W + n * 32 + ((kq ^ (n & 7)) << 2)) * 4,
                      key_in + (size_t)n * 32768 + (size_t)b * 512 + k0 + (kq << 2));
        }
        asm volatile("cp.async.commit_group;" ::: "memory");
    };

    float acc[2][4][4];
    #pragma unroll
    for (int i = 0; i < 2; i++)
        #pragma unroll
        for (int j = 0; j < 4; j++)
            #pragma unroll
            for (int uu = 0; uu < 4; uu++) acc[i][j][uu] = 0.f;

    issue1(0); issue1(1);
    for (int c = 0; c < 16; ++c){
        if (c + 1 < 16) asm volatile("cp.async.wait_group 1;" ::: "memory");
        else            asm volatile("cp.async.wait_group 0;" ::: "memory");
        __syncthreads();
        if (c + 2 < 16) issue1(c + 2);
        const uint32_t* Au = reinterpret_cast<const uint32_t*>(smemf + (c % 3) * STG);
        const uint32_t* Bu = Au + A_W;
        #pragma unroll
        for (int ks = 0; ks < 4; ks++){
            const int kk = ks << 3;
            const int cb = kk >> 2;
            uint32_t af[2][4];
            #pragma unroll
            for (int ma = 0; ma < 2; ma++){
                const int r0 = warp_m * 32 + ma * 16 + g;
                const int r1 = r0 + 8;
                af[ma][0] = Au[r0 * 32 + ((cb ^ g) << 2) + tig];
                af[ma][1] = Au[r1 * 32 + ((cb ^ g) << 2) + tig];
                af[ma][2] = Au[r0 * 32 + (((cb + 1) ^ g) << 2) + tig];
                af[ma][3] = Au[r1 * 32 + (((cb + 1) ^ g) << 2) + tig];
            }
            uint32_t bf[4][2];
            #pragma unroll
            for (int na = 0; na < 4; na++){
                const int cl = warp_n * 32 + na * 8 + g;    // cl & 7 == g
                bf[na][0] = Bu[cl * 32 + ((cb ^ g) << 2) + tig];
                bf[na][1] = Bu[cl * 32 + (((cb + 1) ^ g) << 2) + tig];
            }
            #pragma unroll
            for (int ma = 0; ma < 2; ma++)
                #pragma unroll
                for (int na = 0; na < 4; na++)
                    MMA_TF32(acc[ma][na], af[ma], bf[na]);
        }
        __syncthreads();
    }

    // ---------------- softmax over s (rows = mh) ----------------
    #pragma unroll
    for (int ma = 0; ma < 2; ma++)
        #pragma unroll
        for (int na = 0; na < 4; na++)
            #pragma unroll
            for (int uu = 0; uu < 4; uu++) acc[ma][na][uu] *= 0.125f;

    float* red = smemf + RED;
    float rmax[2][2], rsum[2][2];
    #pragma unroll
    for (int ma = 0; ma < 2; ma++)
        #pragma unroll
        for (int hh = 0; hh < 2; hh++){
            float m = -1e30f;
            #pragma unroll
            for (int na = 0; na < 4; na++)
                m = fmaxf(m, fmaxf(acc[ma][na][2*hh], acc[ma][na][2*hh+1]));
            m = fmaxf(m, __shfl_xor_sync(0xffffffffu, m, 1));
            m = fmaxf(m, __shfl_xor_sync(0xffffffffu, m, 2));
            rmax[ma][hh] = m;
        }
    const int rg = warp_m * 32 + g;
    if (tig == 0){
        red[warp_n * 64 + rg]      = rmax[0][0];
        red[warp_n * 64 + rg + 8]  = rmax[0][1];
        red[warp_n * 64 + rg + 16] = rmax[1][0];
        red[warp_n * 64 + rg + 24] = rmax[1][1];
    }
    __syncthreads();
    #pragma unroll
    for (int ma = 0; ma < 2; ma++)
        #pragma unroll
        for (int hh = 0; hh < 2; hh++){
            const int row = rg + ma * 16 + hh * 8;
            rmax[ma][hh] = fmaxf(fmaxf(red[row], red[64 + row]),
                                 fmaxf(red[128 + row], red[192 + row]));
        }
    __syncthreads();
    #pragma unroll
    for (int ma = 0; ma < 2; ma++)
        #pragma unroll
        for (int hh = 0; hh < 2; hh++){
            float s = 0.f;
            #pragma unroll
            for (int na = 0; na < 4; na++){
                float e0 = __expf(acc[ma][na][2*hh]   - rmax[ma][hh]);
                float e1 = __expf(acc[ma][na][2*hh+1] - rmax[ma][hh]);
                acc[ma][na][2*hh] = e0; acc[ma][na][2*hh+1] = e1;
                s += e0 + e1;
            }
            s += __shfl_xor_sync(0xffffffffu, s, 1);
            s += __shfl_xor_sync(0xffffffffu, s, 2);
            rsum[ma][hh] = s;
        }
    if (tig == 0){
        red[warp_n * 64 + rg]      = rsum[0][0];
        red[warp_n * 64 + rg + 8]  = rsum[0][1];
        red[warp_n * 64 + rg + 16] = rsum[1][0];
        red[warp_n * 64 + rg + 24] = rsum[1][1];
    }
    __syncthreads();
    #pragma unroll
    for (int ma = 0; ma < 2; ma++)
        #pragma unroll
        for (int hh = 0; hh < 2; hh++){
            const int row = rg + ma * 16 + hh * 8;
            rsum[ma][hh] = 1.f / (red[row] + red[64 + row] + red[128 + row] + red[192 + row]);
        }

    // write normalized w (tf32) into WBUF in swizzled-A layout (4 chunks of 64x32)
    uint32_t* wb = reinterpret_cast<uint32_t*>(smemf + WBUF);
    #pragma unroll
    for (int ma = 0; ma < 2; ma++)
        #pragma unroll
        for (int hh = 0; hh < 2; hh++){
            const int row = rg + ma * 16 + hh * 8;
            #pragma unroll
            for (int na = 0; na < 4; na++){
                const int c0 = warp_n * 32 + na * 8 + 2 * tig;   // chunk = warp_n
                const int kc = c0 & 31;
                uint2 v = make_uint2(cvt_tf32(acc[ma][na][2*hh]   * rsum[ma][hh]),
                                     cvt_tf32(acc[ma][na][2*hh+1] * rsum[ma][hh]));
                const int word = warp_n * 2048 + row * 32
                               + (((kc >> 2) ^ (row & 7)) << 2) + (kc & 3);
                *reinterpret_cast<uint2*>(wb + word) = v;
            }
        }
    __syncthreads();

    // ---------------- phase 2: wv = w @ value_in[:,b,:] ----------------
    auto issue2 = [&](int cc){
        const int n0 = (cc >> 2) << 7;
        const int k0 = (cc & 3) << 5;
        const uint32_t sb = sbase + (uint32_t)(cc % 3) * (STG * 4) + A_W * 4;
        #pragma unroll
        for (int i = 0; i < 4; i++){
            int f = tid + (i << 8); int k = f >> 5, nq = f & 31;
            cpasync16(sb + (uint32_t)(k * 132 + (nq << 2)) * 4,
                      value_in + (size_t)(k0 + k) * 32768 + (size_t)b * 512 + n0 + (nq << 2));
        }
        asm volatile("cp.async.commit_group;" ::: "memory");
    };

    float acc2[2][4][4];
    #pragma unroll
    for (int i = 0; i < 2; i++)
        #pragma unroll
        for (int j = 0; j < 4; j++)
            #pragma unroll
            for (int uu = 0; uu < 4; uu++) acc2[i][j][uu] = 0.f;

    issue2(0); issue2(1);
    for (int cc = 0; cc < 16; ++cc){
        if (cc + 1 < 16) asm volatile("cp.async.wait_group 1;" ::: "memory");
        else             asm volatile("cp.async.wait_group 0;" ::: "memory");
        __syncthreads();
        if (cc + 2 < 16) issue2(cc + 2);
        const int kc = cc & 3;
        const uint32_t* Au = wb + kc * 2048;
        const uint32_t* Bu = reinterpret_cast<const uint32_t*>(smemf + (cc % 3) * STG) + A_W;
        #pragma unroll
        for (int ks = 0; ks < 4; ks++){
            const int kk = ks << 3;
            const int cb = kk >> 2;
            uint32_t af[2][4];
            #pragma unroll
            for (int ma = 0; ma < 2; ma++){
                const int r0 = warp_m * 32 + ma * 16 + g;
                const int r1 = r0 + 8;
                af[ma][0] = Au[r0 * 32 + ((cb ^ g) << 2) + tig];
                af[ma][1] = Au[r1 * 32 + ((cb ^ g) << 2) + tig];
                af[ma][2] = Au[r0 * 32 + (((cb + 1) ^ g) << 2) + tig];
                af[ma][3] = Au[r1 * 32 + (((cb + 1) ^ g) << 2) + tig];
            }
            uint32_t bf[4][2];
            #pragma unroll
            for (int na = 0; na < 4; na++){
                const int cl = warp_n * 32 + na * 8 + g;
                bf[na][0] = Bu[(kk + tig) * 132 + cl];
                bf[na][1] = Bu[(kk + tig + 4) * 132 + cl];
            }
            #pragma unroll
            for (int ma = 0; ma < 2; ma++)
                #pragma unroll
                for (int na = 0; na < 4; na++)
                    MMA_TF32(acc2[ma][na], af[ma], bf[na]);
        }
        __syncthreads();
        if (kc == 3){
            const int n0 = (cc >> 2) << 7;
            #pragma unroll
            for (int ma = 0; ma < 2; ma++){
                const int r0 = warp_m * 32 + ma * 16 + g;
                #pragma unroll
                for (int na = 0; na < 4; na++){
                    const int cl = warp_n * 32 + na * 8 + 2 * tig;
                    *reinterpret_cast<float2*>(wvb + (size_t)b * 32768 + (size_t)r0 * 512 + n0 + cl) =
                        make_float2(acc2[ma][na][0], acc2[ma][na][1]);
                    *reinterpret_cast<float2*>(wvb + (size_t)b * 32768 + (size_t)(r0 + 8) * 512 + n0 + cl) =
                        make_float2(acc2[ma][na][2], acc2[ma][na][3]);
                    acc2[ma][na][0] = acc2[ma][na][1] = acc2[ma][na][2] = acc2[ma][na][3] = 0.f;
                }
            }
        }
    }
}

// ===========================================================================
// LDG+cvt double-buffered tf32 GEMM, NT (B K-contiguous): step 2 only (K=64).
// ===========================================================================
template<int ACT, bool BNT, int BN>
__global__ __launch_bounds__(256) void mma_gemm_kernel(
    const float* __restrict__ A, int lda, int sA1, int sA0,
    const float* __restrict__ W, int ldw, int sW1, int sW0,
    float* __restrict__ C, int ldc, int sC1, int sC0,
    const float* __restrict__ bias, int sB1, int sB0,
    int K, int inner)
{
    extern __shared__ float smemf[];
    constexpr int A_F = 64 * 36;
    constexpr int BSTR = BN + 4;
    constexpr int STAGE_F = A_F + 32 * BSTR;

    const int tid = threadIdx.x;
    const int wid = tid >> 5, lane = tid & 31;
    const int g = lane >> 2, tig = lane & 3;
    const int warp_m = wid >> 2;
    const int warp_n = wid & 3;
    const int batch = blockIdx.y;
    const int b1 = batch / inner;
    const int b0 = batch - b1 * inner;
    const int n0 = blockIdx.x * BN;

    const float* Ab = A + (size_t)b1 * sA1 + (size_t)b0 * sA0;
    const float* Wb = W + (size_t)b1 * sW1 + (size_t)b0 * sW0
                        + (BNT ? (size_t)n0 * ldw : (size_t)n0);
    float*       Cb = C + (size_t)b1 * sC1 + (size_t)b0 * sC0 + n0;
    const float* Bb = bias ? bias + (size_t)b1 * sB1 + (size_t)b0 * sB0 + n0 : nullptr;

    const int NC = K >> 5;
    constexpr int BITER = BN / 32;

    float4 aR[2], bR[BITER];
    auto ldg = [&](int c){
        const int k0 = c << 5;
        #pragma unroll
        for (int i = 0; i < 2; i++){
            int f = tid + (i << 8);
            int r = f >> 3, kq = f & 7;
            aR[i] = *reinterpret_cast<const float4*>(Ab + (size_t)r * lda + k0 + (kq << 2));
        }
        #pragma unroll
        for (int i = 0; i < BITER; i++){
            int f = tid + (i << 8);
            if (BNT){
                int n = f >> 3, kq = f & 7;
                bR[i] = *reinterpret_cast<const float4*>(Wb + (size_t)n * ldw + k0 + (kq << 2));
            } else {
                int k = f / (BN >> 2), nq = f % (BN >> 2);
                bR[i] = *reinterpret_cast<const float4*>(Wb + (size_t)(k0 + k) * ldw + (nq << 2));
            }
        }
    };
    auto sts = [&](int s){
        uint32_t* Au = reinterpret_cast<uint32_t*>(smemf + s * STAGE_F);
        uint32_t* Bu = reinterpret_cast<uint32_t*>(smemf + s * STAGE_F + A_F);
        #pragma unroll
        for (int i = 0; i < 2; i++){
            int f = tid + (i << 8);
            int r = f >> 3, kq = f & 7;
            uint4 v = make_uint4(cvt_tf32(aR[i].x), cvt_tf32(aR[i].y),
                                 cvt_tf32(aR[i].z), cvt_tf32(aR[i].w));
            *reinterpret_cast<uint4*>(&Au[r * 36 + (kq << 2)]) = v;
        }
        #pragma unroll
        for (int i = 0; i < BITER; i++){
            int f = tid + (i << 8);
            if (BNT){
                int n = f >> 3, kq = f & 7;
                Bu[(4 * kq + 0) * BSTR + n] = cvt_tf32(bR[i].x);
                Bu[(4 * kq + 1) * BSTR + n] = cvt_tf32(bR[i].y);
                Bu[(4 * kq + 2) * BSTR + n] = cvt_tf32(bR[i].z);
                Bu[(4 * kq + 3) * BSTR + n] = cvt_tf32(bR[i].w);
            } else {
                int k = f / (BN >> 2), nq = f % (BN >> 2);
                uint4 v = make_uint4(cvt_tf32(bR[i].x), cvt_tf32(bR[i].y),
                                     cvt_tf32(bR[i].z), cvt_tf32(bR[i].w));
                *reinterpret_cast<uint4*>(&Bu[k * BSTR + (nq << 2)]) = v;
            }
        }
    };

    constexpr int NA = BN / 32;
    float acc[2][NA][4];
    #pragma unroll
    for (int i = 0; i < 2; i++)
        #pragma unroll
        for (int j = 0; j < NA; j++)
            #pragma unroll
            for (int u = 0; u < 4; u++) acc[i][j][u] = 0.f;

    ldg(0);
    sts(0);
    if (NC > 1) ldg(1);
    __syncthreads();

    for (int c = 0; c < NC; ++c){
        const int s = c & 1;
        if (c + 1 < NC){
            sts(s ^ 1);
            if (c + 2 < NC) ldg(c + 2);
        }
        const uint32_t* Au = reinterpret_cast<const uint32_t*>(smemf + s * STAGE_F);
        const uint32_t* Bu = reinterpret_cast<const uint32_t*>(smemf + s * STAGE_F + A_F);
        #pragma unroll
        for (int ks = 0; ks < 4; ks++){
            const int kk = ks << 3;
            uint32_t af[2][4];
            #pragma unroll
            for (int ma = 0; ma < 2; ma++){
                const int r0 = warp_m * 32 + ma * 16 + g;
                af[ma][0] = Au[r0 * 36 + kk + tig];
                af[ma][1] = Au[(r0 + 8) * 36 + kk + tig];
                af[ma][2] = Au[r0 * 36 + kk + tig + 4];
                af[ma][3] = Au[(r0 + 8) * 36 + kk + tig + 4];
            }
            uint32_t bf[NA][2];
            #pragma unroll
            for (int na = 0; na < NA; na++){
                const int cl = warp_n * (BN / 4) + na * 8 + g;
                bf[na][0] = Bu[(kk + tig) * BSTR + cl];
                bf[na][1] = Bu[(kk + tig + 4) * BSTR + cl];
            }
            #pragma unroll
            for (int ma = 0; ma < 2; ma++)
                #pragma unroll
                for (int na = 0; na < NA; na++)
                    MMA_TF32(acc[ma][na], af[ma], bf[na]);
        }
        __syncthreads();
    }

    #pragma unroll
    for (int ma = 0; ma < 2; ma++){
        const int r0 = warp_m * 32 + ma * 16 + g;
        #pragma unroll
        for (int na = 0; na < NA; na++){
            const int cl = warp_n * (BN / 4) + na * 8 + 2 * tig;
            float b0v = Bb ? Bb[cl] : 0.f;
            float b1v = Bb ? Bb[cl + 1] : 0.f;
            float v0 = acc[ma][na][0] + b0v, v1 = acc[ma][na][1] + b1v;
            float v2 = acc[ma][na][2] + b0v, v3 = acc[ma][na][3] + b1v;
            if (ACT >= 1){
                v0 = fmaxf(v0, 0.f); v1 = fmaxf(v1, 0.f);
                v2 = fmaxf(v2, 0.f); v3 = fmaxf(v3, 0.f);
            }
            *reinterpret_cast<float2*>(Cb + (size_t)r0 * ldc + cl) = make_float2(v0, v1);
            *reinterpret_cast<float2*>(Cb + (size_t)(r0 + 8) * ldc + cl) = make_float2(v2, v3);
        }
    }
}

extern "C" void kernel_launch(void* const* d_in, const int* in_sizes, int n_in,
                              void* d_out, int out_size)
{
    (void)in_sizes; (void)n_in; (void)out_size;
    const float* prev_state = (const float*)d_in[0];
    const float* prev_query = (const float*)d_in[1];
    const float* prev_key   = (const float*)d_in[2];
    const float* prev_value = (const float*)d_in[3];
    const float* key_in     = (const float*)d_in[4];
    const float* value_in   = (const float*)d_in[5];
    const float* Wq = (const float*)d_in[6];
    const float* bq = (const float*)d_in[7];
    const float* Wk = (const float*)d_in[8];
    // d_in[9] = bk: softmax invariant to per-(m,b,h) shift over s -> unused.
    const float* Wv = (const float*)d_in[10];
    const float* bv = (const float*)d_in[11];
    const float* Wo = (const float*)d_in[12];
    const float* bo = (const float*)d_in[13];
    const float* W1  = (const float*)d_in[14];
    const float* b1  = (const float*)d_in[15];
    const float* W2  = (const float*)d_in[16];
    const float* b2  = (const float*)d_in[17];
    const float* Wg1 = (const float*)d_in[18];
    const float* bg1 = (const float*)d_in[19];
    const float* Wg2 = (const float*)d_in[20];
    const float* bg2 = (const float*)d_in[21];
    float* out = (float*)d_out;

    float* scratch = nullptr;
    cudaGetSymbolAddress((void**)&scratch, g_scratch);
    float* q     = scratch;
    float* u     = scratch + 262144;
    float* wvb   = scratch + 2883584;
    float* ao    = scratch + 4980736;
    float* x     = scratch + 5242880;
    float* h     = scratch + 5767168;
    float* gatez = scratch + 7864320;   // [8][32][64]

    const float* NOB = nullptr;
    EpiArgs E0{};

    const int ASM128 = (3 * (64 * 32 + 32 * 132) + 256) * 4;   // 76288
    const int ASM64  = (3 * (64 * 32 + 32 * 68) + 256) * 4;    // 51712
    const int NTSM128 = 2 * (64 * 36 + 32 * 132) * 4;          // 52224
    const int FSM = (3 * 6272 + 8192 + 256) * 4;               // 109056
    cudaFuncSetAttribute(mma_async_kernel<0,128,0>, cudaFuncAttributeMaxDynamicSharedMemorySize, ASM128);
    cudaFuncSetAttribute(mma_async_kernel<0, 64,0>, cudaFuncAttributeMaxDynamicSharedMemorySize, ASM64);
    cudaFuncSetAttribute(mma_async_kernel<1,128,4>, cudaFuncAttributeMaxDynamicSharedMemorySize, ASM128);
    cudaFuncSetAttribute(mma_async_kernel<1,128,3>, cudaFuncAttributeMaxDynamicSharedMemorySize, ASM128);
    cudaFuncSetAttribute(mma_async_kernel<2,128,2>, cudaFuncAttributeMaxDynamicSharedMemorySize, ASM128);
    cudaFuncSetAttribute(mma_gemm_kernel<0,true,128>, cudaFuncAttributeMaxDynamicSharedMemorySize, NTSM128);
    cudaFuncSetAttribute(fused_attn_kernel, cudaFuncAttributeMaxDynamicSharedMemorySize, FSM);

    // 1) q = prev_query @ Wq + bq
    mma_async_kernel<0,128,0><<<dim3(4,8),256,ASM128>>>(
        prev_query,512,32768,0,  Wq,512,262144,0,  q,512,32768,0,  bq,512,0,  512,1, E0);

    // 2) u[b][mh][d] = sum_j q[m][b][h64+j] * Wk[m][d][h64+j]
    mma_gemm_kernel<0,true,128><<<dim3(4,64),256,NTSM128>>>(
        q,512,32768,64,  Wk,512,262144,64,  u,32768,4096,512,  NOB,0,0,  64,8);

    // 3-5) fused scores -> softmax -> wv  (per batch b)
    fused_attn_kernel<<<64,256,FSM>>>(u, key_in, value_in, wvb);

    // 6) ao = wv @ Wv-slices + bv
    mma_async_kernel<0,64,0><<<dim3(1,64),256,ASM64>>>(
        wvb,32768,4096,512,  Wv,512,262144,64,  ao,512,32768,64,  bv,512,64,  512,8, E0);

    // 7) x[:, :D] = relu(ao @ Wo + bo); x[:, D:] = relu(prev_state)  (EPI4)
    {
        EpiArgs E4{};
        E4.p3 = prev_state;
        mma_async_kernel<1,128,4><<<dim3(4,8),256,ASM128>>>(
            ao,512,32768,0,  Wo,512,262144,0,  x,1024,65536,0,  bo,512,0,  512,1, E4);
    }

    // 8) dual MLP: bx<8 -> h = relu(x@W1+b1); bx>=8 -> gate partials via Wg1/bg1/Wg2
    {
        EpiArgs E3{};
        E3.wg2 = Wg2; E3.gatez = gatez; E3.wAlt = Wg1; E3.bAlt = bg1;
        mma_async_kernel<1,128,3><<<dim3(16,32),256,ASM128>>>(
            x,1024,0,65536,  W1,1024,8388608,1048576,  h,1024,524288,65536,  b1,8192,1024,  1024,8, E3);
    }

    // 9) final: v=tanh(relu(h@W2+b2)); gv=sigmoid(sum gatez + bg2); mix with prev
    {
        EpiArgs E2{};
        E2.gzin = gatez; E2.bg2 = bg2;
        E2.p0 = prev_query; E2.p1 = prev_key; E2.p2 = prev_value; E2.p3 = prev_state;
        mma_async_kernel<2,128,2><<<dim3(4,32),256,ASM128>>>(
            h,1024,524288,65536,  W2,512,4194304,524288,  out,512,0,0,  b2,4096,512,  1024,8, E2);
    }
}

// round 13
// speedup vs baseline: 3.0650x; 1.0210x over previous
#include <cuda_runtime.h>
#include <cuda_bf16.h>
#include <math.h>
#include <stdint.h>

// Problem constants: M=8 modules, B=64 batch, S=128 seq, D=512, H=8 heads (hd=64), FF=1024.

// Scratch (static device array; no runtime allocation).
__device__ float g_scratch[11012096];

__device__ __forceinline__ uint32_t smem_u32(const void* p){
    uint32_t a;
    asm("{ .reg .u64 t; cvta.to.shared.u64 t, %1; cvt.u32.u64 %0, t; }" : "=r"(a) : "l"(p));
    return a;
}
__device__ __forceinline__ void cpasync16(uint32_t dst, const float* src){
    asm volatile("cp.async.cg.shared.global [%0], [%1], 16;" :: "r"(dst), "l"(src) : "memory");
}
__device__ __forceinline__ uint32_t cvt_tf32(float x){
    uint32_t r; asm("cvt.rna.tf32.f32 %0, %1;" : "=r"(r) : "f"(x)); return r;
}
// PDL: block until predecessor kernel's writes are visible (implicit trigger at
// predecessor completion). Launched with programmaticStreamSerializationAllowed.
__device__ __forceinline__ void pdl_wait(){
    asm volatile("griddepcontrol.wait;" ::: "memory");
}
#define MMA_TF32(acc, af, bf) \
    asm volatile( \
        "mma.sync.aligned.m16n8k8.row.col.f32.tf32.tf32.f32 " \
        "{%0,%1,%2,%3}, {%4,%5,%6,%7}, {%8,%9}, {%0,%1,%2,%3};" \
        : "+f"((acc)[0]), "+f"((acc)[1]), "+f"((acc)[2]), "+f"((acc)[3]) \
        : "r"((af)[0]), "r"((af)[1]), "r"((af)[2]), "r"((af)[3]), \
          "r"((bf)[0]), "r"((bf)[1]))

struct EpiArgs {
    const float* wg2;    // gate: Wg2 base [4*M][FF]
    float*       gatez;  // gate: partial sums [8][32][64]
    const float* gzin;   // EPI2: gate partials (read)
    const float* bg2;    // EPI2: [4*M]
    const float* p0; const float* p1; const float* p2; const float* p3;  // prev q,k,v,state
    const float* wAlt;   // EPI3: Wg1
    const float* bAlt;   // EPI3: bg1
};

// ===========================================================================
// cp.async 3-stage tf32 mma GEMM (NN: W rows n-contiguous), PDL-aware:
// weight (B) loads for stages 0,1 are issued BEFORE griddepcontrol.wait —
// they never depend on the predecessor; A loads after.
//   C[64 x N] = act( A[64 x K] @ W[K x N] + bias )  per batch (b1,b0)
// A swizzled in SMEM: (r,k) at word r*32 + ((k>>2 ^ (r&7))<<2) + (k&3).
// EPI: 0 = store C
//      2 = final combine (tanh/gate/prev-mix, writes d_out)
//      3 = dual MLP: blockIdx.x<8 -> store C (h); >=8 -> gate partial
//      4 = store C + x[:,512+n] = relu(prev_state)  (concat fold-in)
// ===========================================================================
template<int ACT, int BN, int EPI>
__global__ __launch_bounds__(256) void mma_async_kernel(
    const float* __restrict__ A, int lda, int sA1, int sA0,
    const float* __restrict__ W, int ldw, int sW1, int sW0,
    float* __restrict__ C, int ldc, int sC1, int sC0,
    const float* __restrict__ bias, int sB1, int sB0,
    int K, int inner, EpiArgs epi)
{
    extern __shared__ float smemf[];
    constexpr int A_F = 64 * 32;
    constexpr int BSTR = BN + 4;
    constexpr int B_F = 32 * BSTR;
    constexpr int STAGE_F = A_F + B_F;
    constexpr int BITER = BN / 32;
    constexpr int NA = BN / 32;

    const int tid = threadIdx.x;
    const int wid = tid >> 5, lane = tid & 31;
    const int g = lane >> 2, tig = lane & 3;
    const int warp_m = wid >> 2;
    const int warp_n = wid & 3;
    const int batch = blockIdx.y;
    const int b1 = batch / inner;
    const int b0 = batch - b1 * inner;
    const int nx = (EPI == 3) ? (blockIdx.x & 7) : blockIdx.x;
    const int n0 = nx * BN;
    const bool gp = (EPI == 3) && (blockIdx.x >= 8);

    const float* Wsel = gp ? epi.wAlt : W;
    const float* Bsel = gp ? epi.bAlt : bias;

    const float* Ab = A + (size_t)b1 * sA1 + (size_t)b0 * sA0;
    const float* Wb = Wsel + (size_t)b1 * sW1 + (size_t)b0 * sW0 + n0;
    const float* Bb = Bsel ? Bsel + (size_t)b1 * sB1 + (size_t)b0 * sB0 + n0 : nullptr;
    float* Cb;
    if (EPI == 2)
        Cb = C + (size_t)(((b1 + 1) & 3)) * 262144 + (size_t)b0 * 32768 + n0;
    else
        Cb = C + (size_t)b1 * sC1 + (size_t)b0 * sC0 + n0;

    const uint32_t sbase = smem_u32(smemf);
    const int NC = K >> 5;

    auto issueA = [&](int c){
        const int k0 = c << 5;
        const uint32_t sb = sbase + (uint32_t)(c % 3) * (STAGE_F * 4);
        #pragma unroll
        for (int i = 0; i < 2; i++){
            int f = tid + (i << 8);
            int r = f >> 3, kq = f & 7;
            cpasync16(sb + (uint32_t)(r * 32 + ((kq ^ (r & 7)) << 2)) * 4,
                      Ab + (size_t)r * lda + k0 + (kq << 2));
        }
    };
    auto issueB = [&](int c){
        const int k0 = c << 5;
        const uint32_t sb = sbase + (uint32_t)(c % 3) * (STAGE_F * 4);
        #pragma unroll
        for (int i = 0; i < BITER; i++){
            int f = tid + (i << 8);
            int k = f / (BN >> 2), nq = f % (BN >> 2);
            cpasync16(sb + (uint32_t)(A_F + k * BSTR + (nq << 2)) * 4,
                      Wb + (size_t)(k0 + k) * ldw + (nq << 2));
        }
    };

    float acc[2][NA][4];
    #pragma unroll
    for (int i = 0; i < 2; i++)
        #pragma unroll
        for (int j = 0; j < NA; j++)
            #pragma unroll
            for (int u = 0; u < 4; u++) acc[i][j][u] = 0.f;

    // PDL prologue: stream independent weights first, wait, then A.
    issueB(0);
    issueB(1);
    pdl_wait();
    issueA(0);
    asm volatile("cp.async.commit_group;" ::: "memory");   // g0 = {B0,B1,A0}
    issueA(1);
    asm volatile("cp.async.commit_group;" ::: "memory");   // g1 = {A1}

    for (int c = 0; c < NC; ++c){
        if (c + 1 < NC) asm volatile("cp.async.wait_group 1;" ::: "memory");
        else            asm volatile("cp.async.wait_group 0;" ::: "memory");
        __syncthreads();
        if (c + 2 < NC){
            issueA(c + 2);
            issueB(c + 2);
            asm volatile("cp.async.commit_group;" ::: "memory");
        }

        const uint32_t* Au = reinterpret_cast<const uint32_t*>(smemf + (c % 3) * STAGE_F);
        const uint32_t* Bu = Au + A_F;
        #pragma unroll
        for (int ks = 0; ks < 4; ks++){
            const int kk = ks << 3;
            const int cb = kk >> 2;
            uint32_t af[2][4];
            #pragma unroll
            for (int ma = 0; ma < 2; ma++){
                const int r0 = warp_m * 32 + ma * 16 + g;
                const int r1 = r0 + 8;
                af[ma][0] = Au[r0 * 32 + ((cb ^ g) << 2) + tig];
                af[ma][1] = Au[r1 * 32 + ((cb ^ g) << 2) + tig];
                af[ma][2] = Au[r0 * 32 + (((cb + 1) ^ g) << 2) + tig];
                af[ma][3] = Au[r1 * 32 + (((cb + 1) ^ g) << 2) + tig];
            }
            uint32_t bf[NA][2];
            #pragma unroll
            for (int na = 0; na < NA; na++){
                const int cl = warp_n * (BN / 4) + na * 8 + g;
                bf[na][0] = Bu[(kk + tig) * BSTR + cl];
                bf[na][1] = Bu[(kk + tig + 4) * BSTR + cl];
            }
            #pragma unroll
            for (int ma = 0; ma < 2; ma++)
                #pragma unroll
                for (int na = 0; na < NA; na++)
                    MMA_TF32(acc[ma][na], af[ma], bf[na]);
        }
        __syncthreads();
    }

    if (EPI == 0 || EPI == 4 || (EPI == 3 && !gp)){
        #pragma unroll
        for (int ma = 0; ma < 2; ma++){
            const int r0 = warp_m * 32 + ma * 16 + g;
            #pragma unroll
            for (int na = 0; na < NA; na++){
                const int cl = warp_n * (BN / 4) + na * 8 + 2 * tig;
                float b0v = Bb ? Bb[cl] : 0.f;
                float b1v = Bb ? Bb[cl + 1] : 0.f;
                float v0 = acc[ma][na][0] + b0v, v1 = acc[ma][na][1] + b1v;
                float v2 = acc[ma][na][2] + b0v, v3 = acc[ma][na][3] + b1v;
                if (ACT >= 1){
                    v0 = fmaxf(v0, 0.f); v1 = fmaxf(v1, 0.f);
                    v2 = fmaxf(v2, 0.f); v3 = fmaxf(v3, 0.f);
                }
                if (ACT == 2){
                    v0 = tanhf(v0); v1 = tanhf(v1); v2 = tanhf(v2); v3 = tanhf(v3);
                }
                *reinterpret_cast<float2*>(Cb + (size_t)r0 * ldc + cl) = make_float2(v0, v1);
                *reinterpret_cast<float2*>(Cb + (size_t)(r0 + 8) * ldc + cl) = make_float2(v2, v3);
            }
        }
        if (EPI == 4){
            // fold-in: x[m][b][512 + n0 + cl] = relu(prev_state[m][b][n0 + cl])
            const float* ps = epi.p3 + (size_t)b1 * 32768 + n0;
            #pragma unroll
            for (int ma = 0; ma < 2; ma++){
                const int r0 = warp_m * 32 + ma * 16 + g;
                #pragma unroll
                for (int na = 0; na < NA; na++){
                    const int cl = warp_n * (BN / 4) + na * 8 + 2 * tig;
                    float2 pv0 = *reinterpret_cast<const float2*>(ps + (size_t)r0 * 512 + cl);
                    float2 pv1 = *reinterpret_cast<const float2*>(ps + (size_t)(r0 + 8) * 512 + cl);
                    *reinterpret_cast<float2*>(Cb + 512 + (size_t)r0 * ldc + cl) =
                        make_float2(fmaxf(pv0.x, 0.f), fmaxf(pv0.y, 0.f));
                    *reinterpret_cast<float2*>(Cb + 512 + (size_t)(r0 + 8) * ldc + cl) =
                        make_float2(fmaxf(pv1.x, 0.f), fmaxf(pv1.y, 0.f));
                }
            }
        }
    } else if (EPI == 3){   // gate partial path
        const float* wg2 = epi.wg2 + (size_t)batch * 1024 + n0;
        float* gbuf = smemf + 3 * STAGE_F;      // [4 warp_n][64 rows]
        float s[2][2];
        #pragma unroll
        for (int ma = 0; ma < 2; ma++){ s[ma][0] = 0.f; s[ma][1] = 0.f; }
        #pragma unroll
        for (int na = 0; na < NA; na++){
            const int cl = warp_n * (BN / 4) + na * 8 + 2 * tig;
            const float b0v = Bb[cl], b1v = Bb[cl + 1];
            const float w0 = wg2[cl], w1 = wg2[cl + 1];
            #pragma unroll
            for (int ma = 0; ma < 2; ma++){
                s[ma][0] += fmaxf(acc[ma][na][0] + b0v, 0.f) * w0
                          + fmaxf(acc[ma][na][1] + b1v, 0.f) * w1;
                s[ma][1] += fmaxf(acc[ma][na][2] + b0v, 0.f) * w0
                          + fmaxf(acc[ma][na][3] + b1v, 0.f) * w1;
            }
        }
        #pragma unroll
        for (int ma = 0; ma < 2; ma++)
            #pragma unroll
            for (int hh = 0; hh < 2; hh++){
                s[ma][hh] += __shfl_xor_sync(0xffffffffu, s[ma][hh], 1);
                s[ma][hh] += __shfl_xor_sync(0xffffffffu, s[ma][hh], 2);
            }
        if (tig == 0){
            #pragma unroll
            for (int ma = 0; ma < 2; ma++){
                gbuf[warp_n * 64 + warp_m * 32 + ma * 16 + g]     = s[ma][0];
                gbuf[warp_n * 64 + warp_m * 32 + ma * 16 + g + 8] = s[ma][1];
            }
        }
        __syncthreads();
        if (tid < 64){
            float p = gbuf[tid] + gbuf[64 + tid] + gbuf[128 + tid] + gbuf[192 + tid];
            epi.gatez[((size_t)nx * 32 + batch) * 64 + tid] = p;
        }
    } else if (EPI == 2){   // final combine
        const float bg2v = epi.bg2[batch];
        const float* prev;
        if      (b1 == 0) prev = epi.p0;
        else if (b1 == 1) prev = epi.p1;
        else if (b1 == 2) prev = epi.p2;
        else              prev = epi.p3;
        prev += (size_t)b0 * 32768 + n0;
        #pragma unroll
        for (int ma = 0; ma < 2; ma++){
            const int r0 = warp_m * 32 + ma * 16 + g;
            const int r1 = r0 + 8;
            float gz0 = 0.f, gz1 = 0.f;
            #pragma unroll
            for (int i = 0; i < 8; i++){
                gz0 += epi.gzin[((size_t)i * 32 + batch) * 64 + r0];
                gz1 += epi.gzin[((size_t)i * 32 + batch) * 64 + r1];
            }
            const float gv0 = 1.f / (1.f + __expf(-(gz0 + bg2v)));
            const float gv1 = 1.f / (1.f + __expf(-(gz1 + bg2v)));
            #pragma unroll
            for (int na = 0; na < NA; na++){
                const int cl = warp_n * (BN / 4) + na * 8 + 2 * tig;
                const float b0v = Bb[cl], b1v = Bb[cl + 1];
                float v0 = tanhf(fmaxf(acc[ma][na][0] + b0v, 0.f));
                float v1 = tanhf(fmaxf(acc[ma][na][1] + b1v, 0.f));
                float v2 = tanhf(fmaxf(acc[ma][na][2] + b0v, 0.f));
                float v3 = tanhf(fmaxf(acc[ma][na][3] + b1v, 0.f));
                float2 pA = *reinterpret_cast<const float2*>(prev + (size_t)r0 * 512 + cl);
                float2 pB = *reinterpret_cast<const float2*>(prev + (size_t)r1 * 512 + cl);
                float2 o0 = make_float2(gv0 * v0 + (1.f - gv0) * pA.x,
                                        gv0 * v1 + (1.f - gv0) * pA.y);
                float2 o1 = make_float2(gv1 * v2 + (1.f - gv1) * pB.x,
                                        gv1 * v3 + (1.f - gv1) * pB.y);
                *reinterpret_cast<float2*>(Cb + (size_t)r0 * 512 + cl) = o0;
                *reinterpret_cast<float2*>(Cb + (size_t)r1 * 512 + cl) = o1;
            }
        }
    }
}

// ===========================================================================
// Fused attention core (steps 3+4+5), one CTA per batch b (grid 64):
//   scores[mh][s] = (u[b] @ key_in[:,b,:]^T) * 0.125   (K=512)
//   w = softmax_s(scores); wv[b][mh][d] = w @ value_in[:,b,:]
// PDL: key_in (B) prefetch for stages 0,1 before griddepcontrol.wait; u after.
// ===========================================================================
__global__ __launch_bounds__(256) void fused_attn_kernel(
    const float* __restrict__ u, const float* __restrict__ key_in,
    const float* __restrict__ value_in, float* __restrict__ wvb)
{
    extern __shared__ float smemf[];
    constexpr int A_W  = 2048;            // 64x32 swizzled A
    constexpr int B_W  = 4224;            // max(128x32 swz-NT, 32x132 NN)
    constexpr int STG  = A_W + B_W;       // 6272
    constexpr int WBUF = 3 * STG;         // softmaxed w, 4 chunks of 64x32
    constexpr int RED  = WBUF + 8192;     // [4][64] reduction buffer

    const int tid = threadIdx.x;
    const int wid = tid >> 5, lane = tid & 31;
    const int g = lane >> 2, tig = lane & 3;
    const int warp_m = wid >> 2, warp_n = wid & 3;
    const int b = blockIdx.x;
    const uint32_t sbase = smem_u32(smemf);

    auto issue1A = [&](int c){
        const int k0 = c << 5;
        const uint32_t sb = sbase + (uint32_t)(c % 3) * (STG * 4);
        #pragma unroll
        for (int i = 0; i < 2; i++){
            int f = tid + (i << 8); int r = f >> 3, kq = f & 7;
            cpasync16(sb + (uint32_t)(r * 32 + ((kq ^ (r & 7)) << 2)) * 4,
                      u + (size_t)b * 32768 + (size_t)r * 512 + k0 + (kq << 2));
        }
    };
    auto issue1B = [&](int c){
        const int k0 = c << 5;
        const uint32_t sb = sbase + (uint32_t)(c % 3) * (STG * 4);
        #pragma unroll
        for (int i = 0; i < 4; i++){
            int f = tid + (i << 8); int n = f >> 3, kq = f & 7;
            cpasync16(sb + (uint32_t)(A_W + n * 32 + ((kq ^ (n & 7)) << 2)) * 4,
                      key_in + (size_t)n * 32768 + (size_t)b * 512 + k0 + (kq << 2));
        }
    };

    float acc[2][4][4];
    #pragma unroll
    for (int i = 0; i < 2; i++)
        #pragma unroll
        for (int j = 0; j < 4; j++)
            #pragma unroll
            for (int uu = 0; uu < 4; uu++) acc[i][j][uu] = 0.f;

    issue1B(0);
    issue1B(1);
    pdl_wait();
    issue1A(0);
    asm volatile("cp.async.commit_group;" ::: "memory");
    issue1A(1);
    asm volatile("cp.async.commit_group;" ::: "memory");

    for (int c = 0; c < 16; ++c){
        if (c + 1 < 16) asm volatile("cp.async.wait_group 1;" ::: "memory");
        else            asm volatile("cp.async.wait_group 0;" ::: "memory");
        __syncthreads();
        if (c + 2 < 16){
            issue1A(c + 2);
            issue1B(c + 2);
            asm volatile("cp.async.commit_group;" ::: "memory");
        }
        const uint32_t* Au = reinterpret_cast<const uint32_t*>(smemf + (c % 3) * STG);
        const uint32_t* Bu = Au + A_W;
        #pragma unroll
        for (int ks = 0; ks < 4; ks++){
            const int kk = ks << 3;
            const int cb = kk >> 2;
            uint32_t af[2][4];
            #pragma unroll
            for (int ma = 0; ma < 2; ma++){
                const int r0 = warp_m * 32 + ma * 16 + g;
                const int r1 = r0 + 8;
                af[ma][0] = Au[r0 * 32 + ((cb ^ g) << 2) + tig];
                af[ma][1] = Au[r1 * 32 + ((cb ^ g) << 2) + tig];
                af[ma][2] = Au[r0 * 32 + (((cb + 1) ^ g) << 2) + tig];
                af[ma][3] = Au[r1 * 32 + (((cb + 1) ^ g) << 2) + tig];
            }
            uint32_t bf[4][2];
            #pragma unroll
            for (int na = 0; na < 4; na++){
                const int cl = warp_n * 32 + na * 8 + g;    // cl & 7 == g
                bf[na][0] = Bu[cl * 32 + ((cb ^ g) << 2) + tig];
                bf[na][1] = Bu[cl * 32 + (((cb + 1) ^ g) << 2) + tig];
            }
            #pragma unroll
            for (int ma = 0; ma < 2; ma++)
                #pragma unroll
                for (int na = 0; na < 4; na++)
                    MMA_TF32(acc[ma][na], af[ma], bf[na]);
        }
        __syncthreads();
    }

    // ---------------- softmax over s (rows = mh) ----------------
    #pragma unroll
    for (int ma = 0; ma < 2; ma++)
        #pragma unroll
        for (int na = 0; na < 4; na++)
            #pragma unroll
            for (int uu = 0; uu < 4; uu++) acc[ma][na][uu] *= 0.125f;

    float* red = smemf + RED;
    float rmax[2][2], rsum[2][2];
    #pragma unroll
    for (int ma = 0; ma < 2; ma++)
        #pragma unroll
        for (int hh = 0; hh < 2; hh++){
            float m = -1e30f;
            #pragma unroll
            for (int na = 0; na < 4; na++)
                m = fmaxf(m, fmaxf(acc[ma][na][2*hh], acc[ma][na][2*hh+1]));
            m = fmaxf(m, __shfl_xor_sync(0xffffffffu, m, 1));
            m = fmaxf(m, __shfl_xor_sync(0xffffffffu, m, 2));
            rmax[ma][hh] = m;
        }
    const int rg = warp_m * 32 + g;
    if (tig == 0){
        red[warp_n * 64 + rg]      = rmax[0][0];
        red[warp_n * 64 + rg + 8]  = rmax[0][1];
        red[warp_n * 64 + rg + 16] = rmax[1][0];
        red[warp_n * 64 + rg + 24] = rmax[1][1];
    }
    __syncthreads();
    #pragma unroll
    for (int ma = 0; ma < 2; ma++)
        #pragma unroll
        for (int hh = 0; hh < 2; hh++){
            const int row = rg + ma * 16 + hh * 8;
            rmax[ma][hh] = fmaxf(fmaxf(red[row], red[64 + row]),
                                 fmaxf(red[128 + row], red[192 + row]));
        }
    __syncthreads();
    #pragma unroll
    for (int ma = 0; ma < 2; ma++)
        #pragma unroll
        for (int hh = 0; hh < 2; hh++){
            float s = 0.f;
            #pragma unroll
            for (int na = 0; na < 4; na++){
                float e0 = __expf(acc[ma][na][2*hh]   - rmax[ma][hh]);
                float e1 = __expf(acc[ma][na][2*hh+1] - rmax[ma][hh]);
                acc[ma][na][2*hh] = e0; acc[ma][na][2*hh+1] = e1;
                s += e0 + e1;
            }
            s += __shfl_xor_sync(0xffffffffu, s, 1);
            s += __shfl_xor_sync(0xffffffffu, s, 2);
            rsum[ma][hh] = s;
        }
    if (tig == 0){
        red[warp_n * 64 + rg]      = rsum[0][0];
        red[warp_n * 64 + rg + 8]  = rsum[0][1];
        red[warp_n * 64 + rg + 16] = rsum[1][0];
        red[warp_n * 64 + rg + 24] = rsum[1][1];
    }
    __syncthreads();
    #pragma unroll
    for (int ma = 0; ma < 2; ma++)
        #pragma unroll
        for (int hh = 0; hh < 2; hh++){
            const int row = rg + ma * 16 + hh * 8;
            rsum[ma][hh] = 1.f / (red[row] + red[64 + row] + red[128 + row] + red[192 + row]);
        }

    // write normalized w (tf32) into WBUF in swizzled-A layout (4 chunks of 64x32)
    uint32_t* wb = reinterpret_cast<uint32_t*>(smemf + WBUF);
    #pragma unroll
    for (int ma = 0; ma < 2; ma++)
        #pragma unroll
        for (int hh = 0; hh < 2; hh++){
            const int row = rg + ma * 16 + hh * 8;
            #pragma unroll
            for (int na = 0; na < 4; na++){
                const int c0 = warp_n * 32 + na * 8 + 2 * tig;   // chunk = warp_n
                const int kc = c0 & 31;
                uint2 v = make_uint2(cvt_tf32(acc[ma][na][2*hh]   * rsum[ma][hh]),
                                     cvt_tf32(acc[ma][na][2*hh+1] * rsum[ma][hh]));
                const int word = warp_n * 2048 + row * 32
                               + (((kc >> 2) ^ (row & 7)) << 2) + (kc & 3);
                *reinterpret_cast<uint2*>(wb + word) = v;
            }
        }
    __syncthreads();

    // ---------------- phase 2: wv = w @ value_in[:,b,:] ----------------
    auto issue2 = [&](int cc){
        const int n0 = (cc >> 2) << 7;
        const int k0 = (cc & 3) << 5;
        const uint32_t sb = sbase + (uint32_t)(cc % 3) * (STG * 4) + A_W * 4;
        #pragma unroll
        for (int i = 0; i < 4; i++){
            int f = tid + (i << 8); int k = f >> 5, nq = f & 31;
            cpasync16(sb + (uint32_t)(k * 132 + (nq << 2)) * 4,
                      value_in + (size_t)(k0 + k) * 32768 + (size_t)b * 512 + n0 + (nq << 2));
        }
        asm volatile("cp.async.commit_group;" ::: "memory");
    };

    float acc2[2][4][4];
    #pragma unroll
    for (int i = 0; i < 2; i++)
        #pragma unroll
        for (int j = 0; j < 4; j++)
            #pragma unroll
            for (int uu = 0; uu < 4; uu++) acc2[i][j][uu] = 0.f;

    issue2(0); issue2(1);
    for (int cc = 0; cc < 16; ++cc){
        if (cc + 1 < 16) asm volatile("cp.async.wait_group 1;" ::: "memory");
        else             asm volatile("cp.async.wait_group 0;" ::: "memory");
        __syncthreads();
        if (cc + 2 < 16) issue2(cc + 2);
        const int kc = cc & 3;
        const uint32_t* Au = wb + kc * 2048;
        const uint32_t* Bu = reinterpret_cast<const uint32_t*>(smemf + (cc % 3) * STG) + A_W;
        #pragma unroll
        for (int ks = 0; ks < 4; ks++){
            const int kk = ks << 3;
            const int cb = kk >> 2;
            uint32_t af[2][4];
            #pragma unroll
            for (int ma = 0; ma < 2; ma++){
                const int r0 = warp_m * 32 + ma * 16 + g;
                const int r1 = r0 + 8;
                af[ma][0] = Au[r0 * 32 + ((cb ^ g) << 2) + tig];
                af[ma][1] = Au[r1 * 32 + ((cb ^ g) << 2) + tig];
                af[ma][2] = Au[r0 * 32 + (((cb + 1) ^ g) << 2) + tig];
                af[ma][3] = Au[r1 * 32 + (((cb + 1) ^ g) << 2) + tig];
            }
            uint32_t bf[4][2];
            #pragma unroll
            for (int na = 0; na < 4; na++){
                const int cl = warp_n * 32 + na * 8 + g;
                bf[na][0] = Bu[(kk + tig) * 132 + cl];
                bf[na][1] = Bu[(kk + tig + 4) * 132 + cl];
            }
            #pragma unroll
            for (int ma = 0; ma < 2; ma++)
                #pragma unroll
                for (int na = 0; na < 4; na++)
                    MMA_TF32(acc2[ma][na], af[ma], bf[na]);
        }
        __syncthreads();
        if (kc == 3){
            const int n0 = (cc >> 2) << 7;
            #pragma unroll
            for (int ma = 0; ma < 2; ma++){
                const int r0 = warp_m * 32 + ma * 16 + g;
                #pragma unroll
                for (int na = 0; na < 4; na++){
                    const int cl = warp_n * 32 + na * 8 + 2 * tig;
                    *reinterpret_cast<float2*>(wvb + (size_t)b * 32768 + (size_t)r0 * 512 + n0 + cl) =
                        make_float2(acc2[ma][na][0], acc2[ma][na][1]);
                    *reinterpret_cast<float2*>(wvb + (size_t)b * 32768 + (size_t)(r0 + 8) * 512 + n0 + cl) =
                        make_float2(acc2[ma][na][2], acc2[ma][na][3]);
                    acc2[ma][na][0] = acc2[ma][na][1] = acc2[ma][na][2] = acc2[ma][na][3] = 0.f;
                }
            }
        }
    }
}

// ===========================================================================
// LDG+cvt double-buffered tf32 GEMM, NT (B K-contiguous): step 2 only (K=64).
// PDL: wait before any loads (A=q is predecessor-written).
// ===========================================================================
template<int ACT, bool BNT, int BN>
__global__ __launch_bounds__(256) void mma_gemm_kernel(
    const float* __restrict__ A, int lda, int sA1, int sA0,
    const float* __restrict__ W, int ldw, int sW1, int sW0,
    float* __restrict__ C, int ldc, int sC1, int sC0,
    const float* __restrict__ bias, int sB1, int sB0,
    int K, int inner)
{
    extern __shared__ float smemf[];
    constexpr int A_F = 64 * 36;
    constexpr int BSTR = BN + 4;
    constexpr int STAGE_F = A_F + 32 * BSTR;

    const int tid = threadIdx.x;
    const int wid = tid >> 5, lane = tid & 31;
    const int g = lane >> 2, tig = lane & 3;
    const int warp_m = wid >> 2;
    const int warp_n = wid & 3;
    const int batch = blockIdx.y;
    const int b1 = batch / inner;
    const int b0 = batch - b1 * inner;
    const int n0 = blockIdx.x * BN;

    const float* Ab = A + (size_t)b1 * sA1 + (size_t)b0 * sA0;
    const float* Wb = W + (size_t)b1 * sW1 + (size_t)b0 * sW0
                        + (BNT ? (size_t)n0 * ldw : (size_t)n0);
    float*       Cb = C + (size_t)b1 * sC1 + (size_t)b0 * sC0 + n0;
    const float* Bb = bias ? bias + (size_t)b1 * sB1 + (size_t)b0 * sB0 + n0 : nullptr;

    const int NC = K >> 5;
    constexpr int BITER = BN / 32;

    float4 aR[2], bR[BITER];
    auto ldg = [&](int c){
        const int k0 = c << 5;
        #pragma unroll
        for (int i = 0; i < 2; i++){
            int f = tid + (i << 8);
            int r = f >> 3, kq = f & 7;
            aR[i] = *reinterpret_cast<const float4*>(Ab + (size_t)r * lda + k0 + (kq << 2));
        }
        #pragma unroll
        for (int i = 0; i < BITER; i++){
            int f = tid + (i << 8);
            if (BNT){
                int n = f >> 3, kq = f & 7;
                bR[i] = *reinterpret_cast<const float4*>(Wb + (size_t)n * ldw + k0 + (kq << 2));
            } else {
                int k = f / (BN >> 2), nq = f % (BN >> 2);
                bR[i] = *reinterpret_cast<const float4*>(Wb + (size_t)(k0 + k) * ldw + (nq << 2));
            }
        }
    };
    auto sts = [&](int s){
        uint32_t* Au = reinterpret_cast<uint32_t*>(smemf + s * STAGE_F);
        uint32_t* Bu = reinterpret_cast<uint32_t*>(smemf + s * STAGE_F + A_F);
        #pragma unroll
        for (int i = 0; i < 2; i++){
            int f = tid + (i << 8);
            int r = f >> 3, kq = f & 7;
            uint4 v = make_uint4(cvt_tf32(aR[i].x), cvt_tf32(aR[i].y),
                                 cvt_tf32(aR[i].z), cvt_tf32(aR[i].w));
            *reinterpret_cast<uint4*>(&Au[r * 36 + (kq << 2)]) = v;
        }
        #pragma unroll
        for (int i = 0; i < BITER; i++){
            int f = tid + (i << 8);
            if (BNT){
                int n = f >> 3, kq = f & 7;
                Bu[(4 * kq + 0) * BSTR + n] = cvt_tf32(bR[i].x);
                Bu[(4 * kq + 1) * BSTR + n] = cvt_tf32(bR[i].y);
                Bu[(4 * kq + 2) * BSTR + n] = cvt_tf32(bR[i].z);
                Bu[(4 * kq + 3) * BSTR + n] = cvt_tf32(bR[i].w);
            } else {
                int k = f / (BN >> 2), nq = f % (BN >> 2);
                uint4 v = make_uint4(cvt_tf32(bR[i].x), cvt_tf32(bR[i].y),
                                     cvt_tf32(bR[i].z), cvt_tf32(bR[i].w));
                *reinterpret_cast<uint4*>(&Bu[k * BSTR + (nq << 2)]) = v;
            }
        }
    };

    constexpr int NA = BN / 32;
    float acc[2][NA][4];
    #pragma unroll
    for (int i = 0; i < 2; i++)
        #pragma unroll
        for (int j = 0; j < NA; j++)
            #pragma unroll
            for (int u = 0; u < 4; u++) acc[i][j][u] = 0.f;

    pdl_wait();
    ldg(0);
    sts(0);
    if (NC > 1) ldg(1);
    __syncthreads();

    for (int c = 0; c < NC; ++c){
        const int s = c & 1;
        if (c + 1 < NC){
            sts(s ^ 1);
            if (c + 2 < NC) ldg(c + 2);
        }
        const uint32_t* Au = reinterpret_cast<const uint32_t*>(smemf + s * STAGE_F);
        const uint32_t* Bu = reinterpret_cast<const uint32_t*>(smemf + s * STAGE_F + A_F);
        #pragma unroll
        for (int ks = 0; ks < 4; ks++){
            const int kk = ks << 3;
            uint32_t af[2][4];
            #pragma unroll
            for (int ma = 0; ma < 2; ma++){
                const int r0 = warp_m * 32 + ma * 16 + g;
                af[ma][0] = Au[r0 * 36 + kk + tig];
                af[ma][1] = Au[(r0 + 8) * 36 + kk + tig];
                af[ma][2] = Au[r0 * 36 + kk + tig + 4];
                af[ma][3] = Au[(r0 + 8) * 36 + kk + tig + 4];
            }
            uint32_t bf[NA][2];
            #pragma unroll
            for (int na = 0; na < NA; na++){
                const int cl = warp_n * (BN / 4) + na * 8 + g;
                bf[na][0] = Bu[(kk + tig) * BSTR + cl];
                bf[na][1] = Bu[(kk + tig + 4) * BSTR + cl];
            }
            #pragma unroll
            for (int ma = 0; ma < 2; ma++)
                #pragma unroll
                for (int na = 0; na < NA; na++)
                    MMA_TF32(acc[ma][na], af[ma], bf[na]);
        }
        __syncthreads();
    }

    #pragma unroll
    for (int ma = 0; ma < 2; ma++){
        const int r0 = warp_m * 32 + ma * 16 + g;
        #pragma unroll
        for (int na = 0; na < NA; na++){
            const int cl = warp_n * (BN / 4) + na * 8 + 2 * tig;
            float b0v = Bb ? Bb[cl] : 0.f;
            float b1v = Bb ? Bb[cl + 1] : 0.f;
            float v0 = acc[ma][na][0] + b0v, v1 = acc[ma][na][1] + b1v;
            float v2 = acc[ma][na][2] + b0v, v3 = acc[ma][na][3] + b1v;
            if (ACT >= 1){
                v0 = fmaxf(v0, 0.f); v1 = fmaxf(v1, 0.f);
                v2 = fmaxf(v2, 0.f); v3 = fmaxf(v3, 0.f);
            }
            *reinterpret_cast<float2*>(Cb + (size_t)r0 * ldc + cl) = make_float2(v0, v1);
            *reinterpret_cast<float2*>(Cb + (size_t)(r0 + 8) * ldc + cl) = make_float2(v2, v3);
        }
    }
}

// Host-side PDL launcher: programmatic stream serialization lets this kernel
// pre-launch and run its prologue while the predecessor drains.
template<typename F, typename... Args>
static inline void launch_pdl(F f, dim3 grid, dim3 block, size_t smem, Args... args)
{
    cudaLaunchConfig_t cfg = {};
    cfg.gridDim = grid;
    cfg.blockDim = block;
    cfg.dynamicSmemBytes = smem;
    cudaLaunchAttribute attr[1];
    attr[0].id = cudaLaunchAttributeProgrammaticStreamSerialization;
    attr[0].val.programmaticStreamSerializationAllowed = 1;
    cfg.attrs = attr;
    cfg.numAttrs = 1;
    cudaLaunchKernelEx(&cfg, f, args...);
}

extern "C" void kernel_launch(void* const* d_in, const int* in_sizes, int n_in,
                              void* d_out, int out_size)
{
    (void)in_sizes; (void)n_in; (void)out_size;
    const float* prev_state = (const float*)d_in[0];
    const float* prev_query = (const float*)d_in[1];
    const float* prev_key   = (const float*)d_in[2];
    const float* prev_value = (const float*)d_in[3];
    const float* key_in     = (const float*)d_in[4];
    const float* value_in   = (const float*)d_in[5];
    const float* Wq = (const float*)d_in[6];
    const float* bq = (const float*)d_in[7];
    const float* Wk = (const float*)d_in[8];
    // d_in[9] = bk: softmax invariant to per-(m,b,h) shift over s -> unused.
    const float* Wv = (const float*)d_in[10];
    const float* bv = (const float*)d_in[11];
    const float* Wo = (const float*)d_in[12];
    const float* bo = (const float*)d_in[13];
    const float* W1  = (const float*)d_in[14];
    const float* b1  = (const float*)d_in[15];
    const float* W2  = (const float*)d_in[16];
    const float* b2  = (const float*)d_in[17];
    const float* Wg1 = (const float*)d_in[18];
    const float* bg1 = (const float*)d_in[19];
    const float* Wg2 = (const float*)d_in[20];
    const float* bg2 = (const float*)d_in[21];
    float* out = (float*)d_out;

    float* scratch = nullptr;
    cudaGetSymbolAddress((void**)&scratch, g_scratch);
    float* q     = scratch;
    float* u     = scratch + 262144;
    float* wvb   = scratch + 2883584;
    float* ao    = scratch + 4980736;
    float* x     = scratch + 5242880;
    float* h     = scratch + 5767168;
    float* gatez = scratch + 7864320;   // [8][32][64]

    const float* NOB = nullptr;
    EpiArgs E0{};

    const int ASM128 = (3 * (64 * 32 + 32 * 132) + 256) * 4;   // 76288
    const int ASM64  = (3 * (64 * 32 + 32 * 68) + 256) * 4;    // 51712
    const int NTSM128 = 2 * (64 * 36 + 32 * 132) * 4;          // 52224
    const int FSM = (3 * 6272 + 8192 + 256) * 4;               // 109056
    cudaFuncSetAttribute(mma_async_kernel<0,128,0>, cudaFuncAttributeMaxDynamicSharedMemorySize, ASM128);
    cudaFuncSetAttribute(mma_async_kernel<0, 64,0>, cudaFuncAttributeMaxDynamicSharedMemorySize, ASM64);
    cudaFuncSetAttribute(mma_async_kernel<1,128,4>, cudaFuncAttributeMaxDynamicSharedMemorySize, ASM128);
    cudaFuncSetAttribute(mma_async_kernel<1,128,3>, cudaFuncAttributeMaxDynamicSharedMemorySize, ASM128);
    cudaFuncSetAttribute(mma_async_kernel<2,128,2>, cudaFuncAttributeMaxDynamicSharedMemorySize, ASM128);
    cudaFuncSetAttribute(mma_gemm_kernel<0,true,128>, cudaFuncAttributeMaxDynamicSharedMemorySize, NTSM128);
    cudaFuncSetAttribute(fused_attn_kernel, cudaFuncAttributeMaxDynamicSharedMemorySize, FSM);

    // 1) q = prev_query @ Wq + bq
    launch_pdl(mma_async_kernel<0,128,0>, dim3(4,8), dim3(256), ASM128,
        prev_query,512,32768,0,  Wq,512,262144,0,  q,512,32768,0,  bq,512,0,  512,1, E0);

    // 2) u[b][mh][d] = sum_j q[m][b][h64+j] * Wk[m][d][h64+j]
    launch_pdl(mma_gemm_kernel<0,true,128>, dim3(4,64), dim3(256), NTSM128,
        q,512,32768,64,  Wk,512,262144,64,  u,32768,4096,512,  NOB,0,0,  64,8);

    // 3-5) fused scores -> softmax -> wv  (per batch b)
    launch_pdl(fused_attn_kernel, dim3(64), dim3(256), FSM, u, key_in, value_in, wvb);

    // 6) ao = wv @ Wv-slices + bv
    launch_pdl(mma_async_kernel<0,64,0>, dim3(1,64), dim3(256), ASM64,
        wvb,32768,4096,512,  Wv,512,262144,64,  ao,512,32768,64,  bv,512,64,  512,8, E0);

    // 7) x[:, :D] = relu(ao @ Wo + bo); x[:, D:] = relu(prev_state)  (EPI4)
    {
        EpiArgs E4{};
        E4.p3 = prev_state;
        launch_pdl(mma_async_kernel<1,128,4>, dim3(4,8), dim3(256), ASM128,
            ao,512,32768,0,  Wo,512,262144,0,  x,1024,65536,0,  bo,512,0,  512,1, E4);
    }

    // 8) dual MLP: bx<8 -> h = relu(x@W1+b1); bx>=8 -> gate partials via Wg1/bg1/Wg2
    {
        EpiArgs E3{};
        E3.wg2 = Wg2; E3.gatez = gatez; E3.wAlt = Wg1; E3.bAlt = bg1;
        launch_pdl(mma_async_kernel<1,128,3>, dim3(16,32), dim3(256), ASM128,
            x,1024,0,65536,  W1,1024,8388608,1048576,  h,1024,524288,65536,  b1,8192,1024,  1024,8, E3);
    }

    // 9) final: v=tanh(relu(h@W2+b2)); gv=sigmoid(sum gatez + bg2); mix with prev
    {
        EpiArgs E2{};
        E2.gzin = gatez; E2.bg2 = bg2;
        E2.p0 = prev_query; E2.p1 = prev_key; E2.p2 = prev_value; E2.p3 = prev_state;
        launch_pdl(mma_async_kernel<2,128,2>, dim3(4,32), dim3(256), ASM128,
            h,1024,524288,65536,  W2,512,4194304,524288,  out,512,0,0,  b2,4096,512,  1024,8, E2);
    }
}